// round 4
// baseline (speedup 1.0000x reference)
// DeBERTa-v2 forward, fp32 baseline for GB300 (sm_103a).
// Round 1: correctness + a decent SIMT SGEMM. Tensor-core port comes next.

#include <cuda_runtime.h>
#include <math.h>

// ---------------------------------------------------------------- constants
constexpr int BSZ  = 2;
constexpr int SEQ  = 512;
constexpr int HID  = 1024;
constexpr int NHH  = 16;
constexpr int DH   = 64;      // head dim
constexpr int NL   = 4;
constexpr int FFD  = 4096;
constexpr int RR   = 512;     // 2*SPAN
constexpr int NCLS = 14;
constexpr int TOK  = BSZ * SEQ;   // 1024
constexpr float LN_EPS = 1e-7f;

// ---------------------------------------------------------------- scratch (no cudaMalloc allowed)
__device__ float g_x   [TOK * HID];
__device__ float g_q   [TOK * HID];
__device__ float g_k   [TOK * HID];
__device__ float g_v   [TOK * HID];
__device__ float g_ctx [TOK * HID];
__device__ float g_tmp [TOK * FFD];                  // ffn hidden / proj scratch
__device__ float g_sc  [BSZ * NHH * SEQ * SEQ];      // scores -> probs (in place)
__device__ float g_c2p [BSZ * NHH * SEQ * RR];
__device__ float g_p2c [BSZ * NHH * SEQ * RR];
__device__ float g_posk[RR * HID];
__device__ float g_posq[RR * HID];
__device__ float g_rel [RR * HID];                   // LN(rel_emb)
__device__ float g_t   [TOK * HID];                  // head transform
__device__ float g_lg  [TOK * NCLS];                 // logits
__device__ float g_mk  [TOK];                        // attention mask as float
__device__ int   g_idx [SEQ * SEQ];                  // rel bucket index (shared c2p/p2c)

// ---------------------------------------------------------------- helpers
__device__ __forceinline__ float gelu_f(float x) {
    return 0.5f * x * (1.0f + erff(x * 0.70710678118654752f));
}

__device__ __forceinline__ float warp_sum(float v) {
#pragma unroll
    for (int o = 16; o; o >>= 1) v += __shfl_xor_sync(0xffffffffu, v, o);
    return v;
}
__device__ __forceinline__ float warp_max(float v) {
#pragma unroll
    for (int o = 16; o; o >>= 1) v = fmaxf(v, __shfl_xor_sync(0xffffffffu, v, o));
    return v;
}

template <int NT>
__device__ __forceinline__ float blk_sum(float v) {
    __shared__ float sh[NT / 32];
    __shared__ float res;
    v = warp_sum(v);
    int w = threadIdx.x >> 5;
    if ((threadIdx.x & 31) == 0) sh[w] = v;
    __syncthreads();
    if (w == 0) {
        float r = (threadIdx.x < NT / 32) ? sh[threadIdx.x] : 0.0f;
        r = warp_sum(r);
        if (threadIdx.x == 0) res = r;
    }
    __syncthreads();
    return res;
}
template <int NT>
__device__ __forceinline__ float blk_max(float v) {
    __shared__ float sh[NT / 32];
    __shared__ float res;
    v = warp_max(v);
    int w = threadIdx.x >> 5;
    if ((threadIdx.x & 31) == 0) sh[w] = v;
    __syncthreads();
    if (w == 0) {
        float r = (threadIdx.x < NT / 32) ? sh[threadIdx.x] : -3.4e38f;
        r = warp_max(r);
        if (threadIdx.x == 0) res = r;
    }
    __syncthreads();
    return res;
}

// ---------------------------------------------------------------- generic batched SGEMM
// C[z][M,N] = A[z][M,K] * B[z][K,N or N,K] (+bias[N]) (+gelu)
// Per-z offsets: off = (z / zInner) * strideOuter + (z % zInner) * strideInner.
// Requirements (guaranteed by call sites): M % BM == 0, N % BN == 0, K % 8 == 0,
// all pointers / leading dims 16B-aligned for float4.
template <int BM, int BN, int TM, int TN, bool TRANSB, int ACT>
__global__ __launch_bounds__(256) void gemm_k(
    int M, int N, int K,
    const float* __restrict__ A, int lda, long long saO, long long saI,
    const float* __restrict__ B, int ldb, long long sbO, long long sbI,
    float* __restrict__ C, int ldc, long long scO, long long scI,
    const float* __restrict__ bias, int zInner)
{
    constexpr int BK = 8;
    constexpr int GM = TM / 4;
    constexpr int GN = TN / 4;

    int z  = blockIdx.z;
    int zo = z / zInner, zi = z - zo * zInner;
    A += zo * saO + zi * saI;
    B += zo * sbO + zi * sbI;
    C += zo * scO + zi * scI;

    const int bm = blockIdx.y * BM;
    const int bn = blockIdx.x * BN;
    const int tid = threadIdx.x;
    const int tx = tid & 15;       // 16
    const int ty = tid >> 4;       // 16

    __shared__ float As[BK][BM + 4];
    __shared__ float Bs[BK][BN + 4];

    float acc[TM][TN];
#pragma unroll
    for (int i = 0; i < TM; i++)
#pragma unroll
        for (int j = 0; j < TN; j++) acc[i][j] = 0.0f;

    for (int kt = 0; kt < K; kt += BK) {
        // ---- load A tile (BM x 8), stored transposed
        for (int i = tid; i < BM * 2; i += 256) {
            int r  = i >> 1;
            int kh = (i & 1) << 2;
            float4 a4 = *(const float4*)(A + (long long)(bm + r) * lda + kt + kh);
            As[kh + 0][r] = a4.x; As[kh + 1][r] = a4.y;
            As[kh + 2][r] = a4.z; As[kh + 3][r] = a4.w;
        }
        // ---- load B tile (8 x BN)
        if (TRANSB) {
            for (int i = tid; i < BN * 2; i += 256) {
                int n  = i >> 1;
                int kh = (i & 1) << 2;
                float4 b4 = *(const float4*)(B + (long long)(bn + n) * ldb + kt + kh);
                Bs[kh + 0][n] = b4.x; Bs[kh + 1][n] = b4.y;
                Bs[kh + 2][n] = b4.z; Bs[kh + 3][n] = b4.w;
            }
        } else {
            for (int i = tid; i < BN * 2; i += 256) {
                int r = i / (BN / 4);
                int c = (i - r * (BN / 4)) << 2;
                float4 b4 = *(const float4*)(B + (long long)(kt + r) * ldb + bn + c);
                *(float4*)&Bs[r][c] = b4;
            }
        }
        __syncthreads();

#pragma unroll
        for (int kk = 0; kk < BK; kk++) {
            float af[TM], bf[TN];
#pragma unroll
            for (int g = 0; g < GM; g++) {
                float4 t4 = *(const float4*)&As[kk][g * (BM / 2) + (ty << 2)];
                af[g * 4 + 0] = t4.x; af[g * 4 + 1] = t4.y;
                af[g * 4 + 2] = t4.z; af[g * 4 + 3] = t4.w;
            }
#pragma unroll
            for (int g = 0; g < GN; g++) {
                float4 t4 = *(const float4*)&Bs[kk][g * (BN / 2) + (tx << 2)];
                bf[g * 4 + 0] = t4.x; bf[g * 4 + 1] = t4.y;
                bf[g * 4 + 2] = t4.z; bf[g * 4 + 3] = t4.w;
            }
#pragma unroll
            for (int i = 0; i < TM; i++)
#pragma unroll
                for (int j = 0; j < TN; j++)
                    acc[i][j] = fmaf(af[i], bf[j], acc[i][j]);
        }
        __syncthreads();
    }

    // ---- epilogue
#pragma unroll
    for (int gi = 0; gi < GM; gi++)
#pragma unroll
        for (int ii = 0; ii < 4; ii++) {
            int row = bm + gi * (BM / 2) + (ty << 2) + ii;
#pragma unroll
            for (int gj = 0; gj < GN; gj++) {
                int col = bn + gj * (BN / 2) + (tx << 2);
                float4 bv = make_float4(0.f, 0.f, 0.f, 0.f);
                if (bias) bv = *(const float4*)&bias[col];
                float4 o;
                o.x = acc[gi * 4 + ii][gj * 4 + 0] + bv.x;
                o.y = acc[gi * 4 + ii][gj * 4 + 1] + bv.y;
                o.z = acc[gi * 4 + ii][gj * 4 + 2] + bv.z;
                o.w = acc[gi * 4 + ii][gj * 4 + 3] + bv.w;
                if (ACT == 1) {
                    o.x = gelu_f(o.x); o.y = gelu_f(o.y);
                    o.z = gelu_f(o.z); o.w = gelu_f(o.w);
                }
                *(float4*)(C + (long long)row * ldc + col) = o;
            }
        }
}

// ---------------------------------------------------------------- embedding: x = LN(word_emb[id]) * mask
__global__ void embed_kernel(const float* __restrict__ we,
                             const float* __restrict__ gamma, const float* __restrict__ beta,
                             const int* __restrict__ ids, const int* __restrict__ am,
                             float* __restrict__ x, float* __restrict__ mk)
{
    int t = blockIdx.x, tid = threadIdx.x;
    const float4* row = (const float4*)(we + (long long)ids[t] * HID);
    float4 v = row[tid];
    float s  = v.x + v.y + v.z + v.w;
    float sq = v.x * v.x + v.y * v.y + v.z * v.z + v.w * v.w;
    s  = blk_sum<256>(s);
    sq = blk_sum<256>(sq);
    float mu  = s * (1.0f / HID);
    float inv = rsqrtf(sq * (1.0f / HID) - mu * mu + LN_EPS);
    float m = (float)am[t];
    if (tid == 0) mk[t] = m;
    float4 g = ((const float4*)gamma)[tid];
    float4 b = ((const float4*)beta)[tid];
    float4 o;
    o.x = ((v.x - mu) * inv * g.x + b.x) * m;
    o.y = ((v.y - mu) * inv * g.y + b.y) * m;
    o.z = ((v.z - mu) * inv * g.z + b.z) * m;
    o.w = ((v.w - mu) * inv * g.w + b.w) * m;
    ((float4*)(x + (long long)t * HID))[tid] = o;
}

// ---------------------------------------------------------------- generic LN over width HID (optional residual)
__global__ void ln_kernel(const float* __restrict__ in, const float* __restrict__ resid,
                          const float* __restrict__ gamma, const float* __restrict__ beta,
                          float* __restrict__ out)
{
    int row = blockIdx.x, tid = threadIdx.x;
    float4 v = ((const float4*)(in + (long long)row * HID))[tid];
    if (resid) {
        float4 r = ((const float4*)(resid + (long long)row * HID))[tid];
        v.x += r.x; v.y += r.y; v.z += r.z; v.w += r.w;
    }
    float s  = v.x + v.y + v.z + v.w;
    float sq = v.x * v.x + v.y * v.y + v.z * v.z + v.w * v.w;
    s  = blk_sum<256>(s);
    sq = blk_sum<256>(sq);
    float mu  = s * (1.0f / HID);
    float inv = rsqrtf(sq * (1.0f / HID) - mu * mu + LN_EPS);
    float4 g = ((const float4*)gamma)[tid];
    float4 b = ((const float4*)beta)[tid];
    float4 o;
    o.x = (v.x - mu) * inv * g.x + b.x;
    o.y = (v.y - mu) * inv * g.y + b.y;
    o.z = (v.z - mu) * inv * g.z + b.z;
    o.w = (v.w - mu) * inv * g.w + b.w;
    ((float4*)(out + (long long)row * HID))[tid] = o;
}

// ---------------------------------------------------------------- DeBERTa log-bucket relative index
// idx[q*SEQ+k] = clip(bucket(q-k) + 256, 0, 511).  By odd symmetry of bucket(),
// the p2c gather index p2c_idx[k,q] equals this same idx[q,k].
__global__ void rel_idx_kernel(int* __restrict__ idx)
{
    int k = blockIdx.x * blockDim.x + threadIdx.x;
    int q = blockIdx.y;
    int rel = q - k;
    const int mid = 128;
    int ap = (rel > -mid && rel < mid) ? (mid - 1) : (rel < 0 ? -rel : rel);
    int bucket;
    if (ap <= mid) {
        bucket = rel;
    } else {
        float lp = ceilf(logf((float)ap / 128.0f) / logf(511.0f / 128.0f) * 127.0f) + 128.0f;
        float sg = (rel > 0) ? 1.0f : -1.0f;
        bucket = (int)(lp * sg);
    }
    int c = bucket + 256;
    c = min(max(c, 0), 511);
    idx[q * SEQ + k] = c;
}

// ---------------------------------------------------------------- fused gather + mask + softmax (in place on scores)
__global__ void attn_softmax_kernel(float* __restrict__ sc,
                                    const float* __restrict__ c2p, const float* __restrict__ p2c,
                                    const int* __restrict__ idx, const float* __restrict__ mk)
{
    const float invScale = 0.072168783648703221f;  // 1/sqrt(3*64)
    int q = blockIdx.x, h = blockIdx.y, b = blockIdx.z;
    int tid = threadIdx.x;                          // 128
    long long bh = (long long)b * NHH + h;
    float* srow       = sc  + (bh * SEQ + q) * SEQ;
    const float* crow = c2p + (bh * SEQ + q) * RR;
    const float* psl  = p2c + bh * SEQ * RR;
    const int* irow   = idx + q * SEQ;
    float mq = mk[b * SEQ + q];

    float v[4], mm[4];
    float mx = -3.0e38f;
#pragma unroll
    for (int j = 0; j < 4; j++) {
        int k = j * 128 + tid;
        float m = mq * mk[b * SEQ + k];
        mm[j] = m;
        float s = -3.0e38f;
        if (m != 0.0f) {
            int r = irow[k];
            s = (srow[k] + crow[r] + psl[(long long)k * RR + r]) * invScale;
        }
        v[j] = s;
        mx = fmaxf(mx, s);
    }
    mx = blk_max<128>(mx);
    float sum = 0.0f;
#pragma unroll
    for (int j = 0; j < 4; j++) {
        float e = (mm[j] != 0.0f) ? expf(v[j] - mx) : 0.0f;
        v[j] = e;
        sum += e;
    }
    sum = blk_sum<128>(sum);
    float inv = (sum > 0.0f) ? (1.0f / sum) : 0.0f;
#pragma unroll
    for (int j = 0; j < 4; j++) srow[j * 128 + tid] = v[j] * inv;
}

// ---------------------------------------------------------------- decoder: logits = t @ Wd + bd  (N=14, narrow)
__global__ void decoder_kernel(const float* __restrict__ t, const float* __restrict__ Wd,
                               const float* __restrict__ bd, float* __restrict__ logits,
                               float* __restrict__ dout)
{
    int tok = blockIdx.x, tid = threadIdx.x;        // 128 threads
    float acc[NCLS];
#pragma unroll
    for (int c = 0; c < NCLS; c++) acc[c] = 0.0f;
    const float* trow = t + (long long)tok * HID;
    for (int k = tid; k < HID; k += 128) {
        float tv = trow[k];
        const float* w = Wd + (long long)k * NCLS;
#pragma unroll
        for (int c = 0; c < NCLS; c++) acc[c] = fmaf(tv, w[c], acc[c]);
    }
    __shared__ float red[NCLS][128];
#pragma unroll
    for (int c = 0; c < NCLS; c++) red[c][tid] = acc[c];
    __syncthreads();
    if (tid < NCLS) {
        float s = 0.0f;
        for (int i = 0; i < 128; i++) s += red[tid][i];
        s += bd[tid];
        logits[tok * NCLS + tid] = s;
        if (dout) dout[tok * NCLS + tid] = s;
    }
}

// ---------------------------------------------------------------- masked CE loss (single block, deterministic)
__global__ void loss_kernel(const float* __restrict__ logits, const int* __restrict__ labels,
                            const float* __restrict__ mk, float* __restrict__ outLoss)
{
    int t = threadIdx.x;                             // 1024 threads = TOK
    float m = mk[t];
    const float* lr = logits + t * NCLS;
    float mx = -3.0e38f;
#pragma unroll
    for (int c = 0; c < NCLS; c++) mx = fmaxf(mx, lr[c]);
    float s = 0.0f;
#pragma unroll
    for (int c = 0; c < NCLS; c++) s += expf(lr[c] - mx);
    float lse = mx + logf(s);
    float nll = (lse - lr[labels[t]]) * m;
    float ns = blk_sum<1024>(nll);
    float ms = blk_sum<1024>(m);
    if (t == 0 && outLoss) *outLoss = ns / fmaxf(ms, 1.0f);
}

// ---------------------------------------------------------------- host orchestration
extern "C" void kernel_launch(void* const* d_in, const int* in_sizes, int n_in,
                              void* d_out, int out_size)
{
    (void)in_sizes; (void)n_in;
    const float* word_emb = (const float*)d_in[0];
    const float* emb_ln_s = (const float*)d_in[1];
    const float* emb_ln_b = (const float*)d_in[2];
    const float* rel_emb  = (const float*)d_in[3];
    const float* rel_ln_s = (const float*)d_in[4];
    const float* rel_ln_b = (const float*)d_in[5];
    const float* Wq = (const float*)d_in[6];
    const float* bq = (const float*)d_in[7];
    const float* Wk = (const float*)d_in[8];
    const float* bk = (const float*)d_in[9];
    const float* Wv = (const float*)d_in[10];
    const float* bv = (const float*)d_in[11];
    const float* Wo = (const float*)d_in[12];
    const float* bo = (const float*)d_in[13];
    const float* ln1_s = (const float*)d_in[14];
    const float* ln1_b = (const float*)d_in[15];
    const float* W1 = (const float*)d_in[16];
    const float* b1 = (const float*)d_in[17];
    const float* W2 = (const float*)d_in[18];
    const float* b2 = (const float*)d_in[19];
    const float* ln2_s = (const float*)d_in[20];
    const float* ln2_b = (const float*)d_in[21];
    const float* Wt = (const float*)d_in[22];
    const float* bt = (const float*)d_in[23];
    const float* tln_s = (const float*)d_in[24];
    const float* tln_b = (const float*)d_in[25];
    const float* Wd = (const float*)d_in[26];
    const float* bd = (const float*)d_in[27];
    const int* input_ids = (const int*)d_in[28];
    const int* amask     = (const int*)d_in[29];
    const int* labels    = (const int*)d_in[30];

    float *x, *q, *k, *v, *ctx, *tmp, *sc, *c2p, *p2c, *posk, *posq, *rel, *tb, *lg, *mk;
    int* idx;
    { void* p;
      cudaGetSymbolAddress(&p, g_x);    x    = (float*)p;
      cudaGetSymbolAddress(&p, g_q);    q    = (float*)p;
      cudaGetSymbolAddress(&p, g_k);    k    = (float*)p;
      cudaGetSymbolAddress(&p, g_v);    v    = (float*)p;
      cudaGetSymbolAddress(&p, g_ctx);  ctx  = (float*)p;
      cudaGetSymbolAddress(&p, g_tmp);  tmp  = (float*)p;
      cudaGetSymbolAddress(&p, g_sc);   sc   = (float*)p;
      cudaGetSymbolAddress(&p, g_c2p);  c2p  = (float*)p;
      cudaGetSymbolAddress(&p, g_p2c);  p2c  = (float*)p;
      cudaGetSymbolAddress(&p, g_posk); posk = (float*)p;
      cudaGetSymbolAddress(&p, g_posq); posq = (float*)p;
      cudaGetSymbolAddress(&p, g_rel);  rel  = (float*)p;
      cudaGetSymbolAddress(&p, g_t);    tb   = (float*)p;
      cudaGetSymbolAddress(&p, g_lg);   lg   = (float*)p;
      cudaGetSymbolAddress(&p, g_mk);   mk   = (float*)p;
      cudaGetSymbolAddress(&p, g_idx);  idx  = (int*)p;
    }

    float* out_logits = nullptr;
    float* out_loss   = nullptr;
    if (out_size >= TOK * NCLS) {
        out_logits = (float*)d_out;
        if (out_size > TOK * NCLS) out_loss = (float*)d_out + TOK * NCLS;
    } else if (out_size >= 1) {
        out_loss = (float*)d_out;
    }

    // --- preamble
    embed_kernel<<<TOK, 256>>>(word_emb, emb_ln_s, emb_ln_b, input_ids, amask, x, mk);
    ln_kernel<<<RR, 256>>>(rel_emb, nullptr, rel_ln_s, rel_ln_b, rel);
    rel_idx_kernel<<<dim3(SEQ / 256, SEQ), 256>>>(idx);

    const long long SH  = (long long)SEQ * HID;
    const long long SS  = (long long)SEQ * SEQ;
    const long long SR  = (long long)SEQ * RR;

    for (int l = 0; l < NL; l++) {
        const float* Wq_l = Wq + (long long)l * HID * HID;
        const float* Wk_l = Wk + (long long)l * HID * HID;
        const float* Wv_l = Wv + (long long)l * HID * HID;
        const float* Wo_l = Wo + (long long)l * HID * HID;
        const float* bq_l = bq + l * HID;
        const float* bk_l = bk + l * HID;
        const float* bv_l = bv + l * HID;
        const float* bo_l = bo + l * HID;
        const float* W1_l = W1 + (long long)l * HID * FFD;
        const float* b1_l = b1 + l * FFD;
        const float* W2_l = W2 + (long long)l * FFD * HID;
        const float* b2_l = b2 + l * HID;

        // q, k, v projections: [1024,1024] @ [1024,1024]
        gemm_k<64, 128, 4, 8, false, 0><<<dim3(HID / 128, TOK / 64, 1), 256>>>(
            TOK, HID, HID, x, HID, 0, 0, Wq_l, HID, 0, 0, q, HID, 0, 0, bq_l, 1);
        gemm_k<64, 128, 4, 8, false, 0><<<dim3(HID / 128, TOK / 64, 1), 256>>>(
            TOK, HID, HID, x, HID, 0, 0, Wk_l, HID, 0, 0, k, HID, 0, 0, bk_l, 1);
        gemm_k<64, 128, 4, 8, false, 0><<<dim3(HID / 128, TOK / 64, 1), 256>>>(
            TOK, HID, HID, x, HID, 0, 0, Wv_l, HID, 0, 0, v, HID, 0, 0, bv_l, 1);
        // positional key/query projections (share_att_key): [512,1024] @ [1024,1024]
        gemm_k<64, 128, 4, 8, false, 0><<<dim3(HID / 128, RR / 64, 1), 256>>>(
            RR, HID, HID, rel, HID, 0, 0, Wk_l, HID, 0, 0, posk, HID, 0, 0, bk_l, 1);
        gemm_k<64, 128, 4, 8, false, 0><<<dim3(HID / 128, RR / 64, 1), 256>>>(
            RR, HID, HID, rel, HID, 0, 0, Wq_l, HID, 0, 0, posq, HID, 0, 0, bq_l, 1);

        // scores[b,h] = q[b,:,h,:] @ k[b,:,h,:]^T    (z = b*NH + h)
        gemm_k<64, 128, 4, 8, true, 0><<<dim3(SEQ / 128, SEQ / 64, BSZ * NHH), 256>>>(
            SEQ, SEQ, DH,
            q, HID, SH, DH,
            k, HID, SH, DH,
            sc, SEQ, (long long)NHH * SS, SS,
            nullptr, NHH);
        // c2p[b,h] = q[b,:,h,:] @ posk[:,h,:]^T
        gemm_k<64, 128, 4, 8, true, 0><<<dim3(RR / 128, SEQ / 64, BSZ * NHH), 256>>>(
            SEQ, RR, DH,
            q, HID, SH, DH,
            posk, HID, 0, DH,
            c2p, RR, (long long)NHH * SR, SR,
            nullptr, NHH);
        // p2c[b,h] = k[b,:,h,:] @ posq[:,h,:]^T
        gemm_k<64, 128, 4, 8, true, 0><<<dim3(RR / 128, SEQ / 64, BSZ * NHH), 256>>>(
            SEQ, RR, DH,
            k, HID, SH, DH,
            posq, HID, 0, DH,
            p2c, RR, (long long)NHH * SR, SR,
            nullptr, NHH);

        // fused gather + mask + softmax (scores -> probs in place)
        attn_softmax_kernel<<<dim3(SEQ, NHH, BSZ), 128>>>(sc, c2p, p2c, idx, mk);

        // ctx[b,:,h,:] = probs[b,h] @ v[b,:,h,:]
        gemm_k<64, 64, 4, 4, false, 0><<<dim3(DH / 64, SEQ / 64, BSZ * NHH), 256>>>(
            SEQ, DH, SEQ,
            sc, SEQ, (long long)NHH * SS, SS,
            v, HID, SH, DH,
            ctx, HID, SH, DH,
            nullptr, NHH);

        // output projection + residual LN
        gemm_k<64, 128, 4, 8, false, 0><<<dim3(HID / 128, TOK / 64, 1), 256>>>(
            TOK, HID, HID, ctx, HID, 0, 0, Wo_l, HID, 0, 0, tmp, HID, 0, 0, bo_l, 1);
        ln_kernel<<<TOK, 256>>>(x, tmp, ln1_s + l * HID, ln1_b + l * HID, x);

        // FFN
        gemm_k<128, 128, 8, 8, false, 1><<<dim3(FFD / 128, TOK / 128, 1), 256>>>(
            TOK, FFD, HID, x, HID, 0, 0, W1_l, FFD, 0, 0, tmp, FFD, 0, 0, b1_l, 1);
        gemm_k<64, 128, 4, 8, false, 0><<<dim3(HID / 128, TOK / 64, 1), 256>>>(
            TOK, HID, FFD, tmp, FFD, 0, 0, W2_l, HID, 0, 0, ctx, HID, 0, 0, b2_l, 1);
        ln_kernel<<<TOK, 256>>>(x, ctx, ln2_s + l * HID, ln2_b + l * HID, x);
    }

    // head: t = LN(gelu(x @ Wt + bt)); logits = t @ Wd + bd; loss
    gemm_k<64, 128, 4, 8, false, 1><<<dim3(HID / 128, TOK / 64, 1), 256>>>(
        TOK, HID, HID, x, HID, 0, 0, Wt, HID, 0, 0, tmp, HID, 0, 0, bt, 1);
    ln_kernel<<<TOK, 256>>>(tmp, nullptr, tln_s, tln_b, tb);
    decoder_kernel<<<TOK, 128>>>(tb, Wd, bd, lg, out_logits);
    loss_kernel<<<1, 1024>>>(lg, labels, mk, out_loss);
}

// round 6
// speedup vs baseline: 1.7196x; 1.7196x over previous
// DeBERTa-v2 forward on GB300 (sm_103a).
// Round 2 of optimization: all GEMMs on tensor cores via mma.sync bf16 with
// 3-pass hi/lo split (fp32-accurate), fused fp32->bf16 conversion in smem
// staging, batched launches for occupancy.

#include <cuda_runtime.h>
#include <cuda_bf16.h>
#include <math.h>
#include <stdint.h>

// ---------------------------------------------------------------- constants
constexpr int BSZ  = 2;
constexpr int SEQ  = 512;
constexpr int HID  = 1024;
constexpr int NHH  = 16;
constexpr int DH   = 64;      // head dim
constexpr int NL   = 4;
constexpr int FFD  = 4096;
constexpr int RR   = 512;     // 2*SPAN
constexpr int NCLS = 14;
constexpr int TOK  = BSZ * SEQ;   // 1024
constexpr float LN_EPS = 1e-7f;

constexpr long long SH = (long long)SEQ * HID;
constexpr long long SS = (long long)SEQ * SEQ;
constexpr long long SR = (long long)SEQ * RR;

// ---------------------------------------------------------------- scratch
__device__ float g_x   [TOK * HID];
__device__ float g_q   [TOK * HID];
__device__ float g_k   [TOK * HID];
__device__ float g_v   [TOK * HID];
__device__ float g_ctx [TOK * HID];
__device__ float g_tmp [TOK * FFD];
__device__ float g_sc  [BSZ * NHH * SEQ * SEQ];
__device__ float g_c2p [BSZ * NHH * SEQ * RR];
__device__ float g_p2c [BSZ * NHH * SEQ * RR];
__device__ float g_posk[RR * HID];
__device__ float g_posq[RR * HID];
__device__ float g_rel [RR * HID];
__device__ float g_t   [TOK * HID];
__device__ float g_lg  [TOK * NCLS];
__device__ float g_mk  [TOK];
__device__ int   g_idx [SEQ * SEQ];

// ---------------------------------------------------------------- helpers
__device__ __forceinline__ float gelu_f(float x) {
    return 0.5f * x * (1.0f + erff(x * 0.70710678118654752f));
}

__device__ __forceinline__ float warp_sum(float v) {
#pragma unroll
    for (int o = 16; o; o >>= 1) v += __shfl_xor_sync(0xffffffffu, v, o);
    return v;
}
__device__ __forceinline__ float warp_max(float v) {
#pragma unroll
    for (int o = 16; o; o >>= 1) v = fmaxf(v, __shfl_xor_sync(0xffffffffu, v, o));
    return v;
}

template <int NT>
__device__ __forceinline__ float blk_sum(float v) {
    __shared__ float sh[NT / 32];
    __shared__ float res;
    v = warp_sum(v);
    int w = threadIdx.x >> 5;
    if ((threadIdx.x & 31) == 0) sh[w] = v;
    __syncthreads();
    if (w == 0) {
        float r = (threadIdx.x < NT / 32) ? sh[threadIdx.x] : 0.0f;
        r = warp_sum(r);
        if (threadIdx.x == 0) res = r;
    }
    __syncthreads();
    return res;
}
template <int NT>
__device__ __forceinline__ float blk_max(float v) {
    __shared__ float sh[NT / 32];
    __shared__ float res;
    v = warp_max(v);
    int w = threadIdx.x >> 5;
    if ((threadIdx.x & 31) == 0) sh[w] = v;
    __syncthreads();
    if (w == 0) {
        float r = (threadIdx.x < NT / 32) ? sh[threadIdx.x] : -3.4e38f;
        r = warp_max(r);
        if (threadIdx.x == 0) res = r;
    }
    __syncthreads();
    return res;
}

// ---------------------------------------------------------------- mma helpers
__device__ __forceinline__ void ldsm4(uint32_t r[4], const void* p) {
    uint32_t a = (uint32_t)__cvta_generic_to_shared(p);
    asm volatile("ldmatrix.sync.aligned.m8n8.x4.shared.b16 {%0,%1,%2,%3}, [%4];"
                 : "=r"(r[0]), "=r"(r[1]), "=r"(r[2]), "=r"(r[3]) : "r"(a));
}

__device__ __forceinline__ void mma16816(float c[4], const uint32_t a[4],
                                         uint32_t b0, uint32_t b1) {
    asm volatile(
        "mma.sync.aligned.m16n8k16.row.col.f32.bf16.bf16.f32 "
        "{%0,%1,%2,%3}, {%4,%5,%6,%7}, {%8,%9}, {%0,%1,%2,%3};"
        : "+f"(c[0]), "+f"(c[1]), "+f"(c[2]), "+f"(c[3])
        : "r"(a[0]), "r"(a[1]), "r"(a[2]), "r"(a[3]), "r"(b0), "r"(b1));
}

// split fp32 -> (hi, lo) bf16 pair; hi+lo reproduces x to ~2^-18 relative.
__device__ __forceinline__ void split2(float x, float y,
                                       __nv_bfloat162* ph, __nv_bfloat162* pl) {
    __nv_bfloat16 hx = __float2bfloat16_rn(x);
    __nv_bfloat16 hy = __float2bfloat16_rn(y);
    __nv_bfloat16 lx = __float2bfloat16_rn(x - __bfloat162float(hx));
    __nv_bfloat16 ly = __float2bfloat16_rn(y - __bfloat162float(hy));
    *ph = __nv_bfloat162(hx, hy);
    *pl = __nv_bfloat162(lx, ly);
}

// ---------------------------------------------------------------- tensor-core GEMM core
// BM = BN = 64, BK = 32, 256 threads (8 warps as 2 m-rows x 4 n-cols,
// each warp owns a 32x16 sub-tile = 2 m16 tiles x 2 n8 tiles).
// C[bm:bm+64, bn:bn+64] = A[bm:, K] * B (+bias) (+gelu), fp32 in/out,
// internally bf16 hi/lo 3-pass (hh + hl + lh) for ~fp32 accuracy.
// TRANSB: B is [N,K] row-major (i.e. C = A * B^T). else B is [K,N].
// Requires: rows/cols in range (M,N multiples of 64, K multiple of 32),
// 16B alignment of all row starts.
template <bool TRANSB, int ACT>
__device__ __forceinline__ void gemm64_core(
    const float* __restrict__ A, int lda,
    const float* __restrict__ B, int ldb,
    float* __restrict__ C, int ldc,
    const float* __restrict__ bias,
    int K, int bm, int bn)
{
    constexpr int PAD = 40;  // row pitch in bf16 elems (80B: conflict-free ldmatrix)
    __shared__ __align__(16) __nv_bfloat16 Ah[64 * PAD];
    __shared__ __align__(16) __nv_bfloat16 Al[64 * PAD];
    __shared__ __align__(16) __nv_bfloat16 Bh[64 * PAD];
    __shared__ __align__(16) __nv_bfloat16 Bl[64 * PAD];

    const int tid  = threadIdx.x;
    const int lane = tid & 31;
    const int warp = tid >> 5;
    const int wr   = warp >> 2;           // 0..1
    const int wc   = warp & 3;            // 0..3
    const int wm0  = wr * 32;
    const int wn0  = wc * 16;

    float acc[2][2][4];
#pragma unroll
    for (int i = 0; i < 2; i++)
#pragma unroll
        for (int j = 0; j < 2; j++)
#pragma unroll
            for (int t = 0; t < 4; t++) acc[i][j][t] = 0.0f;

    // ldmatrix source addresses (fixed per thread, offset by ks each step)
    const int arow = (lane & 7) + ((lane >> 3) & 1) * 8;
    const int acol = (lane >> 4) * 8;
    const int brow = wn0 + (lane & 7) + (lane >> 4) * 8;
    const int bcol = ((lane >> 3) & 1) * 8;

    for (int kt = 0; kt < K; kt += 32) {
        // ---- stage A tile: 64 rows x 32 k, fp32 -> bf16 hi/lo
#pragma unroll
        for (int u = 0; u < 2; u++) {
            int i = tid + u * 256;
            int r = i >> 3;
            int c = (i & 7) << 2;
            float4 v = *(const float4*)(A + (size_t)(bm + r) * lda + kt + c);
            split2(v.x, v.y, (__nv_bfloat162*)&Ah[r * PAD + c],
                             (__nv_bfloat162*)&Al[r * PAD + c]);
            split2(v.z, v.w, (__nv_bfloat162*)&Ah[r * PAD + c + 2],
                             (__nv_bfloat162*)&Al[r * PAD + c + 2]);
        }
        // ---- stage B tile as [n][k]
        if (TRANSB) {
#pragma unroll
            for (int u = 0; u < 2; u++) {
                int i = tid + u * 256;
                int r = i >> 3;
                int c = (i & 7) << 2;
                float4 v = *(const float4*)(B + (size_t)(bn + r) * ldb + kt + c);
                split2(v.x, v.y, (__nv_bfloat162*)&Bh[r * PAD + c],
                                 (__nv_bfloat162*)&Bl[r * PAD + c]);
                split2(v.z, v.w, (__nv_bfloat162*)&Bh[r * PAD + c + 2],
                                 (__nv_bfloat162*)&Bl[r * PAD + c + 2]);
            }
        } else {
#pragma unroll
            for (int u = 0; u < 2; u++) {
                int i = tid + u * 256;
                int r = i >> 4;                // k row 0..31
                int c = (i & 15) << 2;         // n col 0..60
                float4 v = *(const float4*)(B + (size_t)(kt + r) * ldb + bn + c);
                float vv[4] = {v.x, v.y, v.z, v.w};
#pragma unroll
                for (int j = 0; j < 4; j++) {
                    __nv_bfloat16 h = __float2bfloat16_rn(vv[j]);
                    Bh[(c + j) * PAD + r] = h;
                    Bl[(c + j) * PAD + r] =
                        __float2bfloat16_rn(vv[j] - __bfloat162float(h));
                }
            }
        }
        __syncthreads();

#pragma unroll
        for (int ks = 0; ks < 32; ks += 16) {
            uint32_t ah[2][4], al[2][4], bh[4], bl[4];
#pragma unroll
            for (int t = 0; t < 2; t++) {
                const __nv_bfloat16* pa = &Ah[(wm0 + t * 16 + arow) * PAD + ks + acol];
                const __nv_bfloat16* pl = &Al[(wm0 + t * 16 + arow) * PAD + ks + acol];
                ldsm4(ah[t], pa);
                ldsm4(al[t], pl);
            }
            ldsm4(bh, &Bh[brow * PAD + ks + bcol]);
            ldsm4(bl, &Bl[brow * PAD + ks + bcol]);

#pragma unroll
            for (int i = 0; i < 2; i++)
#pragma unroll
                for (int j = 0; j < 2; j++) {
                    mma16816(acc[i][j], ah[i], bh[2 * j], bh[2 * j + 1]);  // hh
                    mma16816(acc[i][j], ah[i], bl[2 * j], bl[2 * j + 1]);  // hl
                    mma16816(acc[i][j], al[i], bh[2 * j], bh[2 * j + 1]);  // lh
                }
        }
        __syncthreads();
    }

    // ---- epilogue
#pragma unroll
    for (int i = 0; i < 2; i++) {
        int r0 = bm + wm0 + i * 16 + (lane >> 2);
#pragma unroll
        for (int j = 0; j < 2; j++) {
            int c0 = bn + wn0 + j * 8 + 2 * (lane & 3);
            float bx = 0.f, by = 0.f;
            if (bias) { bx = bias[c0]; by = bias[c0 + 1]; }
            float2 o0, o1;
            o0.x = acc[i][j][0] + bx; o0.y = acc[i][j][1] + by;
            o1.x = acc[i][j][2] + bx; o1.y = acc[i][j][3] + by;
            if (ACT == 1) {
                o0.x = gelu_f(o0.x); o0.y = gelu_f(o0.y);
                o1.x = gelu_f(o1.x); o1.y = gelu_f(o1.y);
            }
            *(float2*)(C + (size_t)r0 * ldc + c0)       = o0;
            *(float2*)(C + (size_t)(r0 + 8) * ldc + c0) = o1;
        }
    }
}

// ---------------------------------------------------------------- kernels on top of the core
struct ProjJob { const float* B; const float* bias; float* C; };

// C_z = A @ B_z + bias_z, B is [K,N] row-major. z = blockIdx.z selects the job.
template <int ACT>
__global__ __launch_bounds__(256) void gemm_proj_k(
    int N, int K, const float* __restrict__ A, int lda,
    ProjJob j0, ProjJob j1, ProjJob j2)
{
    ProjJob jb = (blockIdx.z == 0) ? j0 : ((blockIdx.z == 1) ? j1 : j2);
    gemm64_core<false, ACT>(A, lda, jb.B, N, jb.C, N, jb.bias, K,
                            blockIdx.y * 64, blockIdx.x * 64);
}

// fused attention GEMMs: scores / c2p / p2c, all [512,512] = [512,64]@[512,64]^T
// z = g*32 + (b*16 + h), g in {0: scores, 1: c2p, 2: p2c}
__global__ __launch_bounds__(256) void attn_gemm_k(
    const float* __restrict__ q, const float* __restrict__ k,
    const float* __restrict__ posk, const float* __restrict__ posq,
    float* __restrict__ sc, float* __restrict__ c2p, float* __restrict__ p2c)
{
    int z = blockIdx.z;
    int g = z >> 5;
    int i = z & 31;
    int b = i >> 4;
    int h = i & 15;
    long long aOff = (long long)b * SH + h * DH;
    const float* A;
    const float* B;
    float* C;
    if (g == 0)      { A = q + aOff; B = k + aOff;    C = sc  + (long long)i * SS; }
    else if (g == 1) { A = q + aOff; B = posk + h * DH; C = c2p + (long long)i * SR; }
    else             { A = k + aOff; B = posq + h * DH; C = p2c + (long long)i * SR; }
    gemm64_core<true, 0>(A, HID, B, HID, C, 512, nullptr, DH,
                         blockIdx.y * 64, blockIdx.x * 64);
}

// ctx[b,:,h,:] = probs[b,h] @ v[b,:,h,:]   (z = b*16+h)
__global__ __launch_bounds__(256) void ctx_gemm_k(
    const float* __restrict__ sc, const float* __restrict__ v, float* __restrict__ ctx)
{
    int z = blockIdx.z;
    int b = z >> 4;
    int h = z & 15;
    const float* A = sc + (long long)z * SS;
    const float* B = v + (long long)b * SH + h * DH;
    float* C = ctx + (long long)b * SH + h * DH;
    gemm64_core<false, 0>(A, SEQ, B, HID, C, HID, nullptr, SEQ,
                          blockIdx.y * 64, blockIdx.x * 64);
}

// ---------------------------------------------------------------- embedding
__global__ void embed_kernel(const float* __restrict__ we,
                             const float* __restrict__ gamma, const float* __restrict__ beta,
                             const int* __restrict__ ids, const int* __restrict__ am,
                             float* __restrict__ x, float* __restrict__ mk)
{
    int t = blockIdx.x, tid = threadIdx.x;
    const float4* row = (const float4*)(we + (long long)ids[t] * HID);
    float4 v = row[tid];
    float s  = v.x + v.y + v.z + v.w;
    float sq = v.x * v.x + v.y * v.y + v.z * v.z + v.w * v.w;
    s  = blk_sum<256>(s);
    sq = blk_sum<256>(sq);
    float mu  = s * (1.0f / HID);
    float inv = rsqrtf(sq * (1.0f / HID) - mu * mu + LN_EPS);
    float m = (float)am[t];
    if (tid == 0) mk[t] = m;
    float4 g = ((const float4*)gamma)[tid];
    float4 b = ((const float4*)beta)[tid];
    float4 o;
    o.x = ((v.x - mu) * inv * g.x + b.x) * m;
    o.y = ((v.y - mu) * inv * g.y + b.y) * m;
    o.z = ((v.z - mu) * inv * g.z + b.z) * m;
    o.w = ((v.w - mu) * inv * g.w + b.w) * m;
    ((float4*)(x + (long long)t * HID))[tid] = o;
}

// ---------------------------------------------------------------- LN (optional residual)
__global__ void ln_kernel(const float* __restrict__ in, const float* __restrict__ resid,
                          const float* __restrict__ gamma, const float* __restrict__ beta,
                          float* __restrict__ out)
{
    int row = blockIdx.x, tid = threadIdx.x;
    float4 v = ((const float4*)(in + (long long)row * HID))[tid];
    if (resid) {
        float4 r = ((const float4*)(resid + (long long)row * HID))[tid];
        v.x += r.x; v.y += r.y; v.z += r.z; v.w += r.w;
    }
    float s  = v.x + v.y + v.z + v.w;
    float sq = v.x * v.x + v.y * v.y + v.z * v.z + v.w * v.w;
    s  = blk_sum<256>(s);
    sq = blk_sum<256>(sq);
    float mu  = s * (1.0f / HID);
    float inv = rsqrtf(sq * (1.0f / HID) - mu * mu + LN_EPS);
    float4 g = ((const float4*)gamma)[tid];
    float4 b = ((const float4*)beta)[tid];
    float4 o;
    o.x = (v.x - mu) * inv * g.x + b.x;
    o.y = (v.y - mu) * inv * g.y + b.y;
    o.z = (v.z - mu) * inv * g.z + b.z;
    o.w = (v.w - mu) * inv * g.w + b.w;
    ((float4*)(out + (long long)row * HID))[tid] = o;
}

// ---------------------------------------------------------------- DeBERTa log-bucket index
__global__ void rel_idx_kernel(int* __restrict__ idx)
{
    int k = blockIdx.x * blockDim.x + threadIdx.x;
    int q = blockIdx.y;
    int rel = q - k;
    const int mid = 128;
    int ap = (rel > -mid && rel < mid) ? (mid - 1) : (rel < 0 ? -rel : rel);
    int bucket;
    if (ap <= mid) {
        bucket = rel;
    } else {
        float lp = ceilf(logf((float)ap / 128.0f) / logf(511.0f / 128.0f) * 127.0f) + 128.0f;
        float sg = (rel > 0) ? 1.0f : -1.0f;
        bucket = (int)(lp * sg);
    }
    int c = bucket + 256;
    c = min(max(c, 0), 511);
    idx[q * SEQ + k] = c;
}

// ---------------------------------------------------------------- fused gather + mask + softmax
__global__ void attn_softmax_kernel(float* __restrict__ sc,
                                    const float* __restrict__ c2p, const float* __restrict__ p2c,
                                    const int* __restrict__ idx, const float* __restrict__ mk)
{
    const float invScale = 0.072168783648703221f;  // 1/sqrt(3*64)
    int q = blockIdx.x, h = blockIdx.y, b = blockIdx.z;
    int tid = threadIdx.x;                          // 128
    long long bh = (long long)b * NHH + h;
    float* srow       = sc  + (bh * SEQ + q) * SEQ;
    const float* crow = c2p + (bh * SEQ + q) * RR;
    const float* psl  = p2c + bh * SEQ * RR;
    const int* irow   = idx + q * SEQ;
    float mq = mk[b * SEQ + q];

    float v[4], mm[4];
    float mx = -3.0e38f;
#pragma unroll
    for (int j = 0; j < 4; j++) {
        int k = j * 128 + tid;
        float m = mq * mk[b * SEQ + k];
        mm[j] = m;
        float s = -3.0e38f;
        if (m != 0.0f) {
            int r = irow[k];
            s = (srow[k] + crow[r] + psl[(long long)k * RR + r]) * invScale;
        }
        v[j] = s;
        mx = fmaxf(mx, s);
    }
    mx = blk_max<128>(mx);
    float sum = 0.0f;
#pragma unroll
    for (int j = 0; j < 4; j++) {
        float e = (mm[j] != 0.0f) ? expf(v[j] - mx) : 0.0f;
        v[j] = e;
        sum += e;
    }
    sum = blk_sum<128>(sum);
    float inv = (sum > 0.0f) ? (1.0f / sum) : 0.0f;
#pragma unroll
    for (int j = 0; j < 4; j++) srow[j * 128 + tid] = v[j] * inv;
}

// ---------------------------------------------------------------- decoder (N=14)
__global__ void decoder_kernel(const float* __restrict__ t, const float* __restrict__ Wd,
                               const float* __restrict__ bd, float* __restrict__ logits,
                               float* __restrict__ dout)
{
    int tok = blockIdx.x, tid = threadIdx.x;        // 128 threads
    float acc[NCLS];
#pragma unroll
    for (int c = 0; c < NCLS; c++) acc[c] = 0.0f;
    const float* trow = t + (long long)tok * HID;
    for (int k = tid; k < HID; k += 128) {
        float tv = trow[k];
        const float* w = Wd + (long long)k * NCLS;
#pragma unroll
        for (int c = 0; c < NCLS; c++) acc[c] = fmaf(tv, w[c], acc[c]);
    }
    __shared__ float red[NCLS][128];
#pragma unroll
    for (int c = 0; c < NCLS; c++) red[c][tid] = acc[c];
    __syncthreads();
    if (tid < NCLS) {
        float s = 0.0f;
        for (int i = 0; i < 128; i++) s += red[tid][i];
        s += bd[tid];
        logits[tok * NCLS + tid] = s;
        if (dout) dout[tok * NCLS + tid] = s;
    }
}

// ---------------------------------------------------------------- masked CE loss
__global__ void loss_kernel(const float* __restrict__ logits, const int* __restrict__ labels,
                            const float* __restrict__ mk, float* __restrict__ outLoss)
{
    int t = threadIdx.x;                             // 1024 threads = TOK
    float m = mk[t];
    const float* lr = logits + t * NCLS;
    float mx = -3.0e38f;
#pragma unroll
    for (int c = 0; c < NCLS; c++) mx = fmaxf(mx, lr[c]);
    float s = 0.0f;
#pragma unroll
    for (int c = 0; c < NCLS; c++) s += expf(lr[c] - mx);
    float lse = mx + logf(s);
    float nll = (lse - lr[labels[t]]) * m;
    float ns = blk_sum<1024>(nll);
    float ms = blk_sum<1024>(m);
    if (t == 0 && outLoss) *outLoss = ns / fmaxf(ms, 1.0f);
}

// ---------------------------------------------------------------- host orchestration
extern "C" void kernel_launch(void* const* d_in, const int* in_sizes, int n_in,
                              void* d_out, int out_size)
{
    (void)in_sizes; (void)n_in;
    const float* word_emb = (const float*)d_in[0];
    const float* emb_ln_s = (const float*)d_in[1];
    const float* emb_ln_b = (const float*)d_in[2];
    const float* rel_emb  = (const float*)d_in[3];
    const float* rel_ln_s = (const float*)d_in[4];
    const float* rel_ln_b = (const float*)d_in[5];
    const float* Wq = (const float*)d_in[6];
    const float* bq = (const float*)d_in[7];
    const float* Wk = (const float*)d_in[8];
    const float* bk = (const float*)d_in[9];
    const float* Wv = (const float*)d_in[10];
    const float* bv = (const float*)d_in[11];
    const float* Wo = (const float*)d_in[12];
    const float* bo = (const float*)d_in[13];
    const float* ln1_s = (const float*)d_in[14];
    const float* ln1_b = (const float*)d_in[15];
    const float* W1 = (const float*)d_in[16];
    const float* b1 = (const float*)d_in[17];
    const float* W2 = (const float*)d_in[18];
    const float* b2 = (const float*)d_in[19];
    const float* ln2_s = (const float*)d_in[20];
    const float* ln2_b = (const float*)d_in[21];
    const float* Wt = (const float*)d_in[22];
    const float* bt = (const float*)d_in[23];
    const float* tln_s = (const float*)d_in[24];
    const float* tln_b = (const float*)d_in[25];
    const float* Wd = (const float*)d_in[26];
    const float* bd = (const float*)d_in[27];
    const int* input_ids = (const int*)d_in[28];
    const int* amask     = (const int*)d_in[29];
    const int* labels    = (const int*)d_in[30];

    float *x, *q, *k, *v, *ctx, *tmp, *sc, *c2p, *p2c, *posk, *posq, *rel, *tb, *lg, *mk;
    int* idx;
    { void* p;
      cudaGetSymbolAddress(&p, g_x);    x    = (float*)p;
      cudaGetSymbolAddress(&p, g_q);    q    = (float*)p;
      cudaGetSymbolAddress(&p, g_k);    k    = (float*)p;
      cudaGetSymbolAddress(&p, g_v);    v    = (float*)p;
      cudaGetSymbolAddress(&p, g_ctx);  ctx  = (float*)p;
      cudaGetSymbolAddress(&p, g_tmp);  tmp  = (float*)p;
      cudaGetSymbolAddress(&p, g_sc);   sc   = (float*)p;
      cudaGetSymbolAddress(&p, g_c2p);  c2p  = (float*)p;
      cudaGetSymbolAddress(&p, g_p2c);  p2c  = (float*)p;
      cudaGetSymbolAddress(&p, g_posk); posk = (float*)p;
      cudaGetSymbolAddress(&p, g_posq); posq = (float*)p;
      cudaGetSymbolAddress(&p, g_rel);  rel  = (float*)p;
      cudaGetSymbolAddress(&p, g_t);    tb   = (float*)p;
      cudaGetSymbolAddress(&p, g_lg);   lg   = (float*)p;
      cudaGetSymbolAddress(&p, g_mk);   mk   = (float*)p;
      cudaGetSymbolAddress(&p, g_idx);  idx  = (int*)p;
    }

    float* out_logits = nullptr;
    float* out_loss   = nullptr;
    if (out_size >= TOK * NCLS) {
        out_logits = (float*)d_out;
        if (out_size > TOK * NCLS) out_loss = (float*)d_out + TOK * NCLS;
    } else if (out_size >= 1) {
        out_loss = (float*)d_out;
    }

    // --- preamble
    embed_kernel<<<TOK, 256>>>(word_emb, emb_ln_s, emb_ln_b, input_ids, amask, x, mk);
    ln_kernel<<<RR, 256>>>(rel_emb, nullptr, rel_ln_s, rel_ln_b, rel);
    rel_idx_kernel<<<dim3(SEQ / 256, SEQ), 256>>>(idx);

    for (int l = 0; l < NL; l++) {
        const float* Wq_l = Wq + (long long)l * HID * HID;
        const float* Wk_l = Wk + (long long)l * HID * HID;
        const float* Wv_l = Wv + (long long)l * HID * HID;
        const float* Wo_l = Wo + (long long)l * HID * HID;
        const float* bq_l = bq + l * HID;
        const float* bk_l = bk + l * HID;
        const float* bv_l = bv + l * HID;
        const float* bo_l = bo + l * HID;
        const float* W1_l = W1 + (long long)l * HID * FFD;
        const float* b1_l = b1 + l * FFD;
        const float* W2_l = W2 + (long long)l * FFD * HID;
        const float* b2_l = b2 + l * HID;

        // QKV projections, batched (z = 3): [1024,1024] @ [1024,1024]
        {
            ProjJob jq{Wq_l, bq_l, q}, jk{Wk_l, bk_l, k}, jv{Wv_l, bv_l, v};
            gemm_proj_k<0><<<dim3(HID / 64, TOK / 64, 3), 256>>>(HID, HID, x, HID, jq, jk, jv);
        }
        // positional k/q projections, batched (z = 2): [512,1024] @ [1024,1024]
        {
            ProjJob jk{Wk_l, bk_l, posk}, jq{Wq_l, bq_l, posq};
            gemm_proj_k<0><<<dim3(HID / 64, RR / 64, 2), 256>>>(HID, HID, rel, HID, jk, jq, jq);
        }
        // scores + c2p + p2c fused (z = 96)
        attn_gemm_k<<<dim3(SEQ / 64, SEQ / 64, 96), 256>>>(q, k, posk, posq, sc, c2p, p2c);

        // gather + mask + softmax
        attn_softmax_kernel<<<dim3(SEQ, NHH, BSZ), 128>>>(sc, c2p, p2c, idx, mk);

        // ctx = probs @ v (z = 32)
        ctx_gemm_k<<<dim3(1, SEQ / 64, 32), 256>>>(sc, v, ctx);

        // output projection + residual LN
        {
            ProjJob jo{Wo_l, bo_l, tmp};
            gemm_proj_k<0><<<dim3(HID / 64, TOK / 64, 1), 256>>>(HID, HID, ctx, HID, jo, jo, jo);
        }
        ln_kernel<<<TOK, 256>>>(x, tmp, ln1_s + l * HID, ln1_b + l * HID, x);

        // FFN
        {
            ProjJob j1j{W1_l, b1_l, tmp};
            gemm_proj_k<1><<<dim3(FFD / 64, TOK / 64, 1), 256>>>(FFD, HID, x, HID, j1j, j1j, j1j);
        }
        {
            ProjJob j2j{W2_l, b2_l, ctx};
            gemm_proj_k<0><<<dim3(HID / 64, TOK / 64, 1), 256>>>(HID, FFD, tmp, FFD, j2j, j2j, j2j);
        }
        ln_kernel<<<TOK, 256>>>(x, ctx, ln2_s + l * HID, ln2_b + l * HID, x);
    }

    // head: t = LN(gelu(x @ Wt + bt)); logits = t @ Wd + bd; loss
    {
        ProjJob jt{Wt, bt, tmp};
        gemm_proj_k<1><<<dim3(HID / 64, TOK / 64, 1), 256>>>(HID, HID, x, HID, jt, jt, jt);
    }
    ln_kernel<<<TOK, 256>>>(tmp, nullptr, tln_s, tln_b, tb);
    decoder_kernel<<<TOK, 128>>>(tb, Wd, bd, lg, out_logits);
    loss_kernel<<<1, 1024>>>(lg, labels, mk, out_loss);
}

// round 11
// speedup vs baseline: 3.8466x; 2.2369x over previous
// DeBERTa-v2 forward on GB300 (sm_103a).
// Round 3: 128x64 tensor-core tiles, ldmatrix.trans for [K,N] weights
// (vectorized bf16 staging), register-prefetch software pipeline.
// Numerics: bf16 hi/lo 3-pass split (~fp32 accuracy).

#include <cuda_runtime.h>
#include <cuda_bf16.h>
#include <math.h>
#include <stdint.h>

// ---------------------------------------------------------------- constants
constexpr int BSZ  = 2;
constexpr int SEQ  = 512;
constexpr int HID  = 1024;
constexpr int NHH  = 16;
constexpr int DH   = 64;
constexpr int NL   = 4;
constexpr int FFD  = 4096;
constexpr int RR   = 512;
constexpr int NCLS = 14;
constexpr int TOK  = BSZ * SEQ;
constexpr float LN_EPS = 1e-7f;

constexpr long long SH = (long long)SEQ * HID;
constexpr long long SS = (long long)SEQ * SEQ;
constexpr long long SR = (long long)SEQ * RR;

// ---------------------------------------------------------------- scratch
__device__ float g_x   [TOK * HID];
__device__ float g_q   [TOK * HID];
__device__ float g_k   [TOK * HID];
__device__ float g_v   [TOK * HID];
__device__ float g_ctx [TOK * HID];
__device__ float g_tmp [TOK * FFD];
__device__ float g_sc  [BSZ * NHH * SEQ * SEQ];
__device__ float g_c2p [BSZ * NHH * SEQ * RR];
__device__ float g_p2c [BSZ * NHH * SEQ * RR];
__device__ float g_posk[RR * HID];
__device__ float g_posq[RR * HID];
__device__ float g_rel [RR * HID];
__device__ float g_t   [TOK * HID];
__device__ float g_lg  [TOK * NCLS];
__device__ float g_mk  [TOK];
__device__ int   g_idx [SEQ * SEQ];

// ---------------------------------------------------------------- helpers
__device__ __forceinline__ float gelu_f(float x) {
    return 0.5f * x * (1.0f + erff(x * 0.70710678118654752f));
}

__device__ __forceinline__ float warp_sum(float v) {
#pragma unroll
    for (int o = 16; o; o >>= 1) v += __shfl_xor_sync(0xffffffffu, v, o);
    return v;
}
__device__ __forceinline__ float warp_max(float v) {
#pragma unroll
    for (int o = 16; o; o >>= 1) v = fmaxf(v, __shfl_xor_sync(0xffffffffu, v, o));
    return v;
}

template <int NT>
__device__ __forceinline__ float blk_sum(float v) {
    __shared__ float sh[NT / 32];
    __shared__ float res;
    v = warp_sum(v);
    int w = threadIdx.x >> 5;
    if ((threadIdx.x & 31) == 0) sh[w] = v;
    __syncthreads();
    if (w == 0) {
        float r = (threadIdx.x < NT / 32) ? sh[threadIdx.x] : 0.0f;
        r = warp_sum(r);
        if (threadIdx.x == 0) res = r;
    }
    __syncthreads();
    return res;
}
template <int NT>
__device__ __forceinline__ float blk_max(float v) {
    __shared__ float sh[NT / 32];
    __shared__ float res;
    v = warp_max(v);
    int w = threadIdx.x >> 5;
    if ((threadIdx.x & 31) == 0) sh[w] = v;
    __syncthreads();
    if (w == 0) {
        float r = (threadIdx.x < NT / 32) ? sh[threadIdx.x] : -3.4e38f;
        r = warp_max(r);
        if (threadIdx.x == 0) res = r;
    }
    __syncthreads();
    return res;
}

// ---------------------------------------------------------------- mma helpers
__device__ __forceinline__ void ldsm4(uint32_t r[4], const void* p) {
    uint32_t a = (uint32_t)__cvta_generic_to_shared(p);
    asm volatile("ldmatrix.sync.aligned.m8n8.x4.shared.b16 {%0,%1,%2,%3}, [%4];"
                 : "=r"(r[0]), "=r"(r[1]), "=r"(r[2]), "=r"(r[3]) : "r"(a));
}
__device__ __forceinline__ void ldsm4t(uint32_t r[4], const void* p) {
    uint32_t a = (uint32_t)__cvta_generic_to_shared(p);
    asm volatile("ldmatrix.sync.aligned.m8n8.x4.trans.shared.b16 {%0,%1,%2,%3}, [%4];"
                 : "=r"(r[0]), "=r"(r[1]), "=r"(r[2]), "=r"(r[3]) : "r"(a));
}

__device__ __forceinline__ void mma16816(float c[4], const uint32_t a[4],
                                         uint32_t b0, uint32_t b1) {
    asm volatile(
        "mma.sync.aligned.m16n8k16.row.col.f32.bf16.bf16.f32 "
        "{%0,%1,%2,%3}, {%4,%5,%6,%7}, {%8,%9}, {%0,%1,%2,%3};"
        : "+f"(c[0]), "+f"(c[1]), "+f"(c[2]), "+f"(c[3])
        : "r"(a[0]), "r"(a[1]), "r"(a[2]), "r"(a[3]), "r"(b0), "r"(b1));
}

// split fp32 -> (hi, lo) bf16 pair; hi+lo reproduces x to ~2^-17 relative.
__device__ __forceinline__ void split2(float x, float y,
                                       __nv_bfloat162* ph, __nv_bfloat162* pl) {
    __nv_bfloat16 hx = __float2bfloat16_rn(x);
    __nv_bfloat16 hy = __float2bfloat16_rn(y);
    __nv_bfloat16 lx = __float2bfloat16_rn(x - __bfloat162float(hx));
    __nv_bfloat16 ly = __float2bfloat16_rn(y - __bfloat162float(hy));
    *ph = __nv_bfloat162(hx, hy);
    *pl = __nv_bfloat162(lx, ly);
}

// ---------------------------------------------------------------- tensor-core GEMM core
// Block tile BM x BN, BK = 32, 256 threads, 8 warps.
// Warp grid: WM = BM/32 m-warps x WN = 8/WM n-warps; warp tile 32 x (BN/WN).
// fp32 in/out; bf16 hi/lo 3-pass (hh + hl + lh).
// TRANSB: B is [N,K] row-major (C = A*B^T); else B is [K,N] row-major.
// M,N multiples of BM/BN; K multiple of 32; rows 16B aligned.
template <int BM, int BN, bool TRANSB, int ACT>
__device__ __forceinline__ void gemm_core(
    const float* __restrict__ A, int lda,
    const float* __restrict__ B, int ldb,
    float* __restrict__ C, int ldc,
    const float* __restrict__ bias,
    int K, int bm, int bn)
{
    constexpr int PA   = 40;        // A smem pitch (bf16): conflict-free ldmatrix
    constexpr int PBT  = 40;        // B pitch, TRANSB [n][k]
    constexpr int PBN  = BN + 8;    // B pitch, !TRANSB [k][n]  (72 for BN=64)
    constexpr int WM   = BM / 32;
    constexpr int WN   = 8 / WM;
    constexpr int WTN  = BN / WN;   // 32 (BM=128) or 16 (BM=64)
    constexpr int NT   = WTN / 8;   // n8 tiles per warp
    constexpr int NG   = WTN / 16;  // ldmatrix.x4 groups per warp (n)
    constexpr int AV   = BM / 32;   // float4 per thread, A staging
    constexpr int BV   = BN / 32;   // float4 per thread, B staging
    constexpr int BELE = TRANSB ? BN * PBT : 32 * PBN;

    __shared__ __align__(16) __nv_bfloat16 Ah[BM * PA];
    __shared__ __align__(16) __nv_bfloat16 Al[BM * PA];
    __shared__ __align__(16) __nv_bfloat16 Bh[BELE];
    __shared__ __align__(16) __nv_bfloat16 Bl[BELE];

    const int tid  = threadIdx.x;
    const int lane = tid & 31;
    const int warp = tid >> 5;
    const int wr   = warp / WN;
    const int wc   = warp % WN;
    const int wm0  = wr * 32;
    const int wn0  = wc * WTN;

    float acc[2][NT][4];
#pragma unroll
    for (int i = 0; i < 2; i++)
#pragma unroll
        for (int j = 0; j < NT; j++)
#pragma unroll
            for (int t = 0; t < 4; t++) acc[i][j][t] = 0.0f;

    // ldmatrix per-lane source coordinates
    const int arow = (lane & 7) + ((lane >> 3) & 1) * 8;   // A: row within m16
    const int acol = (lane >> 4) * 8;                      // A: k half
    const int brow = (lane & 7) + (lane >> 4) * 8;         // B trans-B path: n row
    const int bcol = ((lane >> 3) & 1) * 8;                // B: k half
    const int btr  = ((lane >> 3) & 1) * 8 + (lane & 7);   // B [k][n] path: k row
    const int btc  = (lane >> 4) * 8;                      // B [k][n] path: n col

    float4 ra[AV], rb[BV];

    auto loadA = [&](int kt) {
#pragma unroll
        for (int u = 0; u < AV; u++) {
            int i = tid + u * 256;
            int r = i >> 3, c = (i & 7) << 2;
            ra[u] = *(const float4*)(A + (size_t)(bm + r) * lda + kt + c);
        }
    };
    auto loadB = [&](int kt) {
        if (TRANSB) {
#pragma unroll
            for (int u = 0; u < BV; u++) {
                int i = tid + u * 256;
                int r = i >> 3, c = (i & 7) << 2;
                rb[u] = *(const float4*)(B + (size_t)(bn + r) * ldb + kt + c);
            }
        } else {
#pragma unroll
            for (int u = 0; u < BV; u++) {
                int i = tid + u * 256;
                int r = i >> 4, c = (i & 15) << 2;
                rb[u] = *(const float4*)(B + (size_t)(kt + r) * ldb + bn + c);
            }
        }
    };
    auto storeA = [&]() {
#pragma unroll
        for (int u = 0; u < AV; u++) {
            int i = tid + u * 256;
            int r = i >> 3, c = (i & 7) << 2;
            split2(ra[u].x, ra[u].y, (__nv_bfloat162*)&Ah[r * PA + c],
                                     (__nv_bfloat162*)&Al[r * PA + c]);
            split2(ra[u].z, ra[u].w, (__nv_bfloat162*)&Ah[r * PA + c + 2],
                                     (__nv_bfloat162*)&Al[r * PA + c + 2]);
        }
    };
    auto storeB = [&]() {
        if (TRANSB) {
#pragma unroll
            for (int u = 0; u < BV; u++) {
                int i = tid + u * 256;
                int r = i >> 3, c = (i & 7) << 2;
                split2(rb[u].x, rb[u].y, (__nv_bfloat162*)&Bh[r * PBT + c],
                                         (__nv_bfloat162*)&Bl[r * PBT + c]);
                split2(rb[u].z, rb[u].w, (__nv_bfloat162*)&Bh[r * PBT + c + 2],
                                         (__nv_bfloat162*)&Bl[r * PBT + c + 2]);
            }
        } else {
#pragma unroll
            for (int u = 0; u < BV; u++) {
                int i = tid + u * 256;
                int r = i >> 4, c = (i & 15) << 2;
                split2(rb[u].x, rb[u].y, (__nv_bfloat162*)&Bh[r * PBN + c],
                                         (__nv_bfloat162*)&Bl[r * PBN + c]);
                split2(rb[u].z, rb[u].w, (__nv_bfloat162*)&Bh[r * PBN + c + 2],
                                         (__nv_bfloat162*)&Bl[r * PBN + c + 2]);
            }
        }
    };

    loadA(0); loadB(0);

    for (int kt = 0; kt < K; kt += 32) {
        storeA(); storeB();
        __syncthreads();
        if (kt + 32 < K) { loadA(kt + 32); loadB(kt + 32); }  // prefetch

#pragma unroll
        for (int ks = 0; ks < 32; ks += 16) {
            uint32_t ah[2][4], al[2][4], bh[NG][4], bl[NG][4];
#pragma unroll
            for (int t = 0; t < 2; t++) {
                ldsm4(ah[t], &Ah[(wm0 + t * 16 + arow) * PA + ks + acol]);
                ldsm4(al[t], &Al[(wm0 + t * 16 + arow) * PA + ks + acol]);
            }
#pragma unroll
            for (int g = 0; g < NG; g++) {
                if (TRANSB) {
                    ldsm4 (bh[g], &Bh[(wn0 + g * 16 + brow) * PBT + ks + bcol]);
                    ldsm4 (bl[g], &Bl[(wn0 + g * 16 + brow) * PBT + ks + bcol]);
                } else {
                    ldsm4t(bh[g], &Bh[(ks + btr) * PBN + wn0 + g * 16 + btc]);
                    ldsm4t(bl[g], &Bl[(ks + btr) * PBN + wn0 + g * 16 + btc]);
                }
            }
#pragma unroll
            for (int i = 0; i < 2; i++)
#pragma unroll
                for (int j = 0; j < NT; j++) {
                    int g = j >> 1, s = (j & 1) * 2;
                    mma16816(acc[i][j], ah[i], bh[g][s], bh[g][s + 1]);  // hh
                    mma16816(acc[i][j], ah[i], bl[g][s], bl[g][s + 1]);  // hl
                    mma16816(acc[i][j], al[i], bh[g][s], bh[g][s + 1]);  // lh
                }
        }
        __syncthreads();
    }

    // ---- epilogue
#pragma unroll
    for (int i = 0; i < 2; i++) {
        int r0 = bm + wm0 + i * 16 + (lane >> 2);
#pragma unroll
        for (int j = 0; j < NT; j++) {
            int c0 = bn + wn0 + j * 8 + 2 * (lane & 3);
            float bx = 0.f, by = 0.f;
            if (bias) { bx = bias[c0]; by = bias[c0 + 1]; }
            float2 o0, o1;
            o0.x = acc[i][j][0] + bx; o0.y = acc[i][j][1] + by;
            o1.x = acc[i][j][2] + bx; o1.y = acc[i][j][3] + by;
            if (ACT == 1) {
                o0.x = gelu_f(o0.x); o0.y = gelu_f(o0.y);
                o1.x = gelu_f(o1.x); o1.y = gelu_f(o1.y);
            }
            *(float2*)(C + (size_t)r0 * ldc + c0)       = o0;
            *(float2*)(C + (size_t)(r0 + 8) * ldc + c0) = o1;
        }
    }
}

// ---------------------------------------------------------------- kernels on top of the core
struct ProjJob { const float* B; const float* bias; float* C; };

// C_z = A @ B_z + bias_z, B is [K,N] row-major; z selects job.
template <int ACT>
__global__ __launch_bounds__(256, 2) void gemm_proj_k(
    int N, int K, const float* __restrict__ A, int lda,
    ProjJob j0, ProjJob j1, ProjJob j2)
{
    ProjJob jb = (blockIdx.z == 0) ? j0 : ((blockIdx.z == 1) ? j1 : j2);
    gemm_core<128, 64, false, ACT>(A, lda, jb.B, N, jb.C, N, jb.bias, K,
                                   blockIdx.y * 128, blockIdx.x * 64);
}

// fused attention GEMMs: scores / c2p / p2c, [512,512] = [512,64] @ [512,64]^T
// z = g*32 + (b*16 + h), g in {0: scores, 1: c2p, 2: p2c}
__global__ __launch_bounds__(256, 2) void attn_gemm_k(
    const float* __restrict__ q, const float* __restrict__ k,
    const float* __restrict__ posk, const float* __restrict__ posq,
    float* __restrict__ sc, float* __restrict__ c2p, float* __restrict__ p2c)
{
    int z = blockIdx.z;
    int g = z >> 5;
    int i = z & 31;
    int b = i >> 4;
    int h = i & 15;
    long long aOff = (long long)b * SH + h * DH;
    const float* A;
    const float* B;
    float* C;
    if (g == 0)      { A = q + aOff; B = k + aOff;      C = sc  + (long long)i * SS; }
    else if (g == 1) { A = q + aOff; B = posk + h * DH; C = c2p + (long long)i * SR; }
    else             { A = k + aOff; B = posq + h * DH; C = p2c + (long long)i * SR; }
    gemm_core<128, 64, true, 0>(A, HID, B, HID, C, 512, nullptr, DH,
                                blockIdx.y * 128, blockIdx.x * 64);
}

// ctx[b,:,h,:] = probs[b,h] @ v[b,:,h,:]   (z = b*16+h)
__global__ __launch_bounds__(256, 2) void ctx_gemm_k(
    const float* __restrict__ sc, const float* __restrict__ v, float* __restrict__ ctx)
{
    int z = blockIdx.z;
    int b = z >> 4;
    int h = z & 15;
    const float* A = sc + (long long)z * SS;
    const float* B = v + (long long)b * SH + h * DH;
    float* C = ctx + (long long)b * SH + h * DH;
    gemm_core<64, 64, false, 0>(A, SEQ, B, HID, C, HID, nullptr, SEQ,
                                blockIdx.y * 64, blockIdx.x * 64);
}

// ---------------------------------------------------------------- embedding
__global__ void embed_kernel(const float* __restrict__ we,
                             const float* __restrict__ gamma, const float* __restrict__ beta,
                             const int* __restrict__ ids, const int* __restrict__ am,
                             float* __restrict__ x, float* __restrict__ mk)
{
    int t = blockIdx.x, tid = threadIdx.x;
    const float4* row = (const float4*)(we + (long long)ids[t] * HID);
    float4 v = row[tid];
    float s  = v.x + v.y + v.z + v.w;
    float sq = v.x * v.x + v.y * v.y + v.z * v.z + v.w * v.w;
    s  = blk_sum<256>(s);
    sq = blk_sum<256>(sq);
    float mu  = s * (1.0f / HID);
    float inv = rsqrtf(sq * (1.0f / HID) - mu * mu + LN_EPS);
    float m = (float)am[t];
    if (tid == 0) mk[t] = m;
    float4 g = ((const float4*)gamma)[tid];
    float4 b = ((const float4*)beta)[tid];
    float4 o;
    o.x = ((v.x - mu) * inv * g.x + b.x) * m;
    o.y = ((v.y - mu) * inv * g.y + b.y) * m;
    o.z = ((v.z - mu) * inv * g.z + b.z) * m;
    o.w = ((v.w - mu) * inv * g.w + b.w) * m;
    ((float4*)(x + (long long)t * HID))[tid] = o;
}

// ---------------------------------------------------------------- LN (optional residual)
__global__ void ln_kernel(const float* __restrict__ in, const float* __restrict__ resid,
                          const float* __restrict__ gamma, const float* __restrict__ beta,
                          float* __restrict__ out)
{
    int row = blockIdx.x, tid = threadIdx.x;
    float4 v = ((const float4*)(in + (long long)row * HID))[tid];
    if (resid) {
        float4 r = ((const float4*)(resid + (long long)row * HID))[tid];
        v.x += r.x; v.y += r.y; v.z += r.z; v.w += r.w;
    }
    float s  = v.x + v.y + v.z + v.w;
    float sq = v.x * v.x + v.y * v.y + v.z * v.z + v.w * v.w;
    s  = blk_sum<256>(s);
    sq = blk_sum<256>(sq);
    float mu  = s * (1.0f / HID);
    float inv = rsqrtf(sq * (1.0f / HID) - mu * mu + LN_EPS);
    float4 g = ((const float4*)gamma)[tid];
    float4 b = ((const float4*)beta)[tid];
    float4 o;
    o.x = (v.x - mu) * inv * g.x + b.x;
    o.y = (v.y - mu) * inv * g.y + b.y;
    o.z = (v.z - mu) * inv * g.z + b.z;
    o.w = (v.w - mu) * inv * g.w + b.w;
    ((float4*)(out + (long long)row * HID))[tid] = o;
}

// ---------------------------------------------------------------- DeBERTa log-bucket index
__global__ void rel_idx_kernel(int* __restrict__ idx)
{
    int k = blockIdx.x * blockDim.x + threadIdx.x;
    int q = blockIdx.y;
    int rel = q - k;
    const int mid = 128;
    int ap = (rel > -mid && rel < mid) ? (mid - 1) : (rel < 0 ? -rel : rel);
    int bucket;
    if (ap <= mid) {
        bucket = rel;
    } else {
        float lp = ceilf(logf((float)ap / 128.0f) / logf(511.0f / 128.0f) * 127.0f) + 128.0f;
        float sg = (rel > 0) ? 1.0f : -1.0f;
        bucket = (int)(lp * sg);
    }
    int c = bucket + 256;
    c = min(max(c, 0), 511);
    idx[q * SEQ + k] = c;
}

// ---------------------------------------------------------------- fused gather + mask + softmax
__global__ void attn_softmax_kernel(float* __restrict__ sc,
                                    const float* __restrict__ c2p, const float* __restrict__ p2c,
                                    const int* __restrict__ idx, const float* __restrict__ mk)
{
    const float invScale = 0.072168783648703221f;  // 1/sqrt(3*64)
    int q = blockIdx.x, h = blockIdx.y, b = blockIdx.z;
    int tid = threadIdx.x;                          // 128
    long long bh = (long long)b * NHH + h;
    float* srow       = sc  + (bh * SEQ + q) * SEQ;
    const float* crow = c2p + (bh * SEQ + q) * RR;
    const float* psl  = p2c + bh * SEQ * RR;
    const int* irow   = idx + q * SEQ;
    float mq = mk[b * SEQ + q];

    float v[4], mm[4];
    float mx = -3.0e38f;
#pragma unroll
    for (int j = 0; j < 4; j++) {
        int k = j * 128 + tid;
        float m = mq * mk[b * SEQ + k];
        mm[j] = m;
        float s = -3.0e38f;
        if (m != 0.0f) {
            int r = irow[k];
            s = (srow[k] + crow[r] + psl[(long long)k * RR + r]) * invScale;
        }
        v[j] = s;
        mx = fmaxf(mx, s);
    }
    mx = blk_max<128>(mx);
    float sum = 0.0f;
#pragma unroll
    for (int j = 0; j < 4; j++) {
        float e = (mm[j] != 0.0f) ? expf(v[j] - mx) : 0.0f;
        v[j] = e;
        sum += e;
    }
    sum = blk_sum<128>(sum);
    float inv = (sum > 0.0f) ? (1.0f / sum) : 0.0f;
#pragma unroll
    for (int j = 0; j < 4; j++) srow[j * 128 + tid] = v[j] * inv;
}

// ---------------------------------------------------------------- decoder (N=14)
__global__ void decoder_kernel(const float* __restrict__ t, const float* __restrict__ Wd,
                               const float* __restrict__ bd, float* __restrict__ logits,
                               float* __restrict__ dout)
{
    int tok = blockIdx.x, tid = threadIdx.x;        // 128 threads
    float acc[NCLS];
#pragma unroll
    for (int c = 0; c < NCLS; c++) acc[c] = 0.0f;
    const float* trow = t + (long long)tok * HID;
    for (int k = tid; k < HID; k += 128) {
        float tv = trow[k];
        const float* w = Wd + (long long)k * NCLS;
#pragma unroll
        for (int c = 0; c < NCLS; c++) acc[c] = fmaf(tv, w[c], acc[c]);
    }
    __shared__ float red[NCLS][128];
#pragma unroll
    for (int c = 0; c < NCLS; c++) red[c][tid] = acc[c];
    __syncthreads();
    if (tid < NCLS) {
        float s = 0.0f;
        for (int i = 0; i < 128; i++) s += red[tid][i];
        s += bd[tid];
        logits[tok * NCLS + tid] = s;
        if (dout) dout[tok * NCLS + tid] = s;
    }
}

// ---------------------------------------------------------------- masked CE loss
__global__ void loss_kernel(const float* __restrict__ logits, const int* __restrict__ labels,
                            const float* __restrict__ mk, float* __restrict__ outLoss)
{
    int t = threadIdx.x;                             // 1024 threads = TOK
    float m = mk[t];
    const float* lr = logits + t * NCLS;
    float mx = -3.0e38f;
#pragma unroll
    for (int c = 0; c < NCLS; c++) mx = fmaxf(mx, lr[c]);
    float s = 0.0f;
#pragma unroll
    for (int c = 0; c < NCLS; c++) s += expf(lr[c] - mx);
    float lse = mx + logf(s);
    float nll = (lse - lr[labels[t]]) * m;
    float ns = blk_sum<1024>(nll);
    float ms = blk_sum<1024>(m);
    if (t == 0 && outLoss) *outLoss = ns / fmaxf(ms, 1.0f);
}

// ---------------------------------------------------------------- host orchestration
extern "C" void kernel_launch(void* const* d_in, const int* in_sizes, int n_in,
                              void* d_out, int out_size)
{
    (void)in_sizes; (void)n_in;
    const float* word_emb = (const float*)d_in[0];
    const float* emb_ln_s = (const float*)d_in[1];
    const float* emb_ln_b = (const float*)d_in[2];
    const float* rel_emb  = (const float*)d_in[3];
    const float* rel_ln_s = (const float*)d_in[4];
    const float* rel_ln_b = (const float*)d_in[5];
    const float* Wq = (const float*)d_in[6];
    const float* bq = (const float*)d_in[7];
    const float* Wk = (const float*)d_in[8];
    const float* bk = (const float*)d_in[9];
    const float* Wv = (const float*)d_in[10];
    const float* bv = (const float*)d_in[11];
    const float* Wo = (const float*)d_in[12];
    const float* bo = (const float*)d_in[13];
    const float* ln1_s = (const float*)d_in[14];
    const float* ln1_b = (const float*)d_in[15];
    const float* W1 = (const float*)d_in[16];
    const float* b1 = (const float*)d_in[17];
    const float* W2 = (const float*)d_in[18];
    const float* b2 = (const float*)d_in[19];
    const float* ln2_s = (const float*)d_in[20];
    const float* ln2_b = (const float*)d_in[21];
    const float* Wt = (const float*)d_in[22];
    const float* bt = (const float*)d_in[23];
    const float* tln_s = (const float*)d_in[24];
    const float* tln_b = (const float*)d_in[25];
    const float* Wd = (const float*)d_in[26];
    const float* bd = (const float*)d_in[27];
    const int* input_ids = (const int*)d_in[28];
    const int* amask     = (const int*)d_in[29];
    const int* labels    = (const int*)d_in[30];

    float *x, *q, *k, *v, *ctx, *tmp, *sc, *c2p, *p2c, *posk, *posq, *rel, *tb, *lg, *mk;
    int* idx;
    { void* p;
      cudaGetSymbolAddress(&p, g_x);    x    = (float*)p;
      cudaGetSymbolAddress(&p, g_q);    q    = (float*)p;
      cudaGetSymbolAddress(&p, g_k);    k    = (float*)p;
      cudaGetSymbolAddress(&p, g_v);    v    = (float*)p;
      cudaGetSymbolAddress(&p, g_ctx);  ctx  = (float*)p;
      cudaGetSymbolAddress(&p, g_tmp);  tmp  = (float*)p;
      cudaGetSymbolAddress(&p, g_sc);   sc   = (float*)p;
      cudaGetSymbolAddress(&p, g_c2p);  c2p  = (float*)p;
      cudaGetSymbolAddress(&p, g_p2c);  p2c  = (float*)p;
      cudaGetSymbolAddress(&p, g_posk); posk = (float*)p;
      cudaGetSymbolAddress(&p, g_posq); posq = (float*)p;
      cudaGetSymbolAddress(&p, g_rel);  rel  = (float*)p;
      cudaGetSymbolAddress(&p, g_t);    tb   = (float*)p;
      cudaGetSymbolAddress(&p, g_lg);   lg   = (float*)p;
      cudaGetSymbolAddress(&p, g_mk);   mk   = (float*)p;
      cudaGetSymbolAddress(&p, g_idx);  idx  = (int*)p;
    }

    float* out_logits = nullptr;
    float* out_loss   = nullptr;
    if (out_size >= TOK * NCLS) {
        out_logits = (float*)d_out;
        if (out_size > TOK * NCLS) out_loss = (float*)d_out + TOK * NCLS;
    } else if (out_size >= 1) {
        out_loss = (float*)d_out;
    }

    // --- preamble
    embed_kernel<<<TOK, 256>>>(word_emb, emb_ln_s, emb_ln_b, input_ids, amask, x, mk);
    ln_kernel<<<RR, 256>>>(rel_emb, nullptr, rel_ln_s, rel_ln_b, rel);
    rel_idx_kernel<<<dim3(SEQ / 256, SEQ), 256>>>(idx);

    for (int l = 0; l < NL; l++) {
        const float* Wq_l = Wq + (long long)l * HID * HID;
        const float* Wk_l = Wk + (long long)l * HID * HID;
        const float* Wv_l = Wv + (long long)l * HID * HID;
        const float* Wo_l = Wo + (long long)l * HID * HID;
        const float* bq_l = bq + l * HID;
        const float* bk_l = bk + l * HID;
        const float* bv_l = bv + l * HID;
        const float* bo_l = bo + l * HID;
        const float* W1_l = W1 + (long long)l * HID * FFD;
        const float* b1_l = b1 + l * FFD;
        const float* W2_l = W2 + (long long)l * FFD * HID;
        const float* b2_l = b2 + l * HID;

        // QKV projections, batched (z = 3)
        {
            ProjJob jq{Wq_l, bq_l, q}, jk{Wk_l, bk_l, k}, jv{Wv_l, bv_l, v};
            gemm_proj_k<0><<<dim3(HID / 64, TOK / 128, 3), 256>>>(HID, HID, x, HID, jq, jk, jv);
        }
        // positional k/q projections, batched (z = 2)
        {
            ProjJob jk{Wk_l, bk_l, posk}, jq{Wq_l, bq_l, posq};
            gemm_proj_k<0><<<dim3(HID / 64, RR / 128, 2), 256>>>(HID, HID, rel, HID, jk, jq, jq);
        }
        // scores + c2p + p2c fused (z = 96)
        attn_gemm_k<<<dim3(SEQ / 64, SEQ / 128, 96), 256>>>(q, k, posk, posq, sc, c2p, p2c);

        // gather + mask + softmax
        attn_softmax_kernel<<<dim3(SEQ, NHH, BSZ), 128>>>(sc, c2p, p2c, idx, mk);

        // ctx = probs @ v (z = 32)
        ctx_gemm_k<<<dim3(1, SEQ / 64, 32), 256>>>(sc, v, ctx);

        // output projection + residual LN
        {
            ProjJob jo{Wo_l, bo_l, tmp};
            gemm_proj_k<0><<<dim3(HID / 64, TOK / 128, 1), 256>>>(HID, HID, ctx, HID, jo, jo, jo);
        }
        ln_kernel<<<TOK, 256>>>(x, tmp, ln1_s + l * HID, ln1_b + l * HID, x);

        // FFN
        {
            ProjJob j1j{W1_l, b1_l, tmp};
            gemm_proj_k<1><<<dim3(FFD / 64, TOK / 128, 1), 256>>>(FFD, HID, x, HID, j1j, j1j, j1j);
        }
        {
            ProjJob j2j{W2_l, b2_l, ctx};
            gemm_proj_k<0><<<dim3(HID / 64, TOK / 128, 1), 256>>>(HID, FFD, tmp, FFD, j2j, j2j, j2j);
        }
        ln_kernel<<<TOK, 256>>>(x, ctx, ln2_s + l * HID, ln2_b + l * HID, x);
    }

    // head: t = LN(gelu(x @ Wt + bt)); logits = t @ Wd + bd; loss
    {
        ProjJob jt{Wt, bt, tmp};
        gemm_proj_k<1><<<dim3(HID / 64, TOK / 128, 1), 256>>>(HID, HID, x, HID, jt, jt, jt);
    }
    ln_kernel<<<TOK, 256>>>(tmp, nullptr, tln_s, tln_b, tb);
    decoder_kernel<<<TOK, 128>>>(tb, Wd, bd, lg, out_logits);
    loss_kernel<<<1, 1024>>>(lg, labels, mk, out_loss);
}

// round 13
// speedup vs baseline: 3.9761x; 1.0337x over previous
// DeBERTa-v2 forward on GB300 (sm_103a).
// Round 4: double-buffered smem pipeline (1 sync/k-tile), merged QKV+pos
// launch, BM=64 tiles for small-grid GEMMs, dynamic smem for 128-row tiles.
// Numerics: bf16 hi/lo 3-pass split (~fp32 accuracy).

#include <cuda_runtime.h>
#include <cuda_bf16.h>
#include <math.h>
#include <stdint.h>

// ---------------------------------------------------------------- constants
constexpr int BSZ  = 2;
constexpr int SEQ  = 512;
constexpr int HID  = 1024;
constexpr int NHH  = 16;
constexpr int DH   = 64;
constexpr int NL   = 4;
constexpr int FFD  = 4096;
constexpr int RR   = 512;
constexpr int NCLS = 14;
constexpr int TOK  = BSZ * SEQ;
constexpr float LN_EPS = 1e-7f;

constexpr long long SH = (long long)SEQ * HID;
constexpr long long SS = (long long)SEQ * SEQ;
constexpr long long SR = (long long)SEQ * RR;

// dynamic smem sizes (bytes) -- must mirror gemm_core layout math
constexpr int SMEM_P128 = 59392;  // BM=128, !TRANSB, BN=64
constexpr int SMEM_T128 = 61440;  // BM=128, TRANSB,  BN=64
constexpr int SMEM_P64  = 38912;  // BM=64,  !TRANSB, BN=64

// ---------------------------------------------------------------- scratch
__device__ float g_x   [TOK * HID];
__device__ float g_q   [TOK * HID];
__device__ float g_k   [TOK * HID];
__device__ float g_v   [TOK * HID];
__device__ float g_ctx [TOK * HID];
__device__ float g_tmp [TOK * FFD];
__device__ float g_sc  [BSZ * NHH * SEQ * SEQ];
__device__ float g_c2p [BSZ * NHH * SEQ * RR];
__device__ float g_p2c [BSZ * NHH * SEQ * RR];
__device__ float g_posk[RR * HID];
__device__ float g_posq[RR * HID];
__device__ float g_rel [RR * HID];
__device__ float g_t   [TOK * HID];
__device__ float g_lg  [TOK * NCLS];
__device__ float g_mk  [TOK];
__device__ int   g_idx [SEQ * SEQ];

// ---------------------------------------------------------------- helpers
__device__ __forceinline__ float gelu_f(float x) {
    return 0.5f * x * (1.0f + erff(x * 0.70710678118654752f));
}

__device__ __forceinline__ float warp_sum(float v) {
#pragma unroll
    for (int o = 16; o; o >>= 1) v += __shfl_xor_sync(0xffffffffu, v, o);
    return v;
}
__device__ __forceinline__ float warp_max(float v) {
#pragma unroll
    for (int o = 16; o; o >>= 1) v = fmaxf(v, __shfl_xor_sync(0xffffffffu, v, o));
    return v;
}

template <int NT>
__device__ __forceinline__ float blk_sum(float v) {
    __shared__ float sh[NT / 32];
    __shared__ float res;
    v = warp_sum(v);
    int w = threadIdx.x >> 5;
    if ((threadIdx.x & 31) == 0) sh[w] = v;
    __syncthreads();
    if (w == 0) {
        float r = (threadIdx.x < NT / 32) ? sh[threadIdx.x] : 0.0f;
        r = warp_sum(r);
        if (threadIdx.x == 0) res = r;
    }
    __syncthreads();
    return res;
}
template <int NT>
__device__ __forceinline__ float blk_max(float v) {
    __shared__ float sh[NT / 32];
    __shared__ float res;
    v = warp_max(v);
    int w = threadIdx.x >> 5;
    if ((threadIdx.x & 31) == 0) sh[w] = v;
    __syncthreads();
    if (w == 0) {
        float r = (threadIdx.x < NT / 32) ? sh[threadIdx.x] : -3.4e38f;
        r = warp_max(r);
        if (threadIdx.x == 0) res = r;
    }
    __syncthreads();
    return res;
}

// ---------------------------------------------------------------- mma helpers
__device__ __forceinline__ void ldsm4(uint32_t r[4], const void* p) {
    uint32_t a = (uint32_t)__cvta_generic_to_shared(p);
    asm volatile("ldmatrix.sync.aligned.m8n8.x4.shared.b16 {%0,%1,%2,%3}, [%4];"
                 : "=r"(r[0]), "=r"(r[1]), "=r"(r[2]), "=r"(r[3]) : "r"(a));
}
__device__ __forceinline__ void ldsm4t(uint32_t r[4], const void* p) {
    uint32_t a = (uint32_t)__cvta_generic_to_shared(p);
    asm volatile("ldmatrix.sync.aligned.m8n8.x4.trans.shared.b16 {%0,%1,%2,%3}, [%4];"
                 : "=r"(r[0]), "=r"(r[1]), "=r"(r[2]), "=r"(r[3]) : "r"(a));
}

__device__ __forceinline__ void mma16816(float c[4], const uint32_t a[4],
                                         uint32_t b0, uint32_t b1) {
    asm volatile(
        "mma.sync.aligned.m16n8k16.row.col.f32.bf16.bf16.f32 "
        "{%0,%1,%2,%3}, {%4,%5,%6,%7}, {%8,%9}, {%0,%1,%2,%3};"
        : "+f"(c[0]), "+f"(c[1]), "+f"(c[2]), "+f"(c[3])
        : "r"(a[0]), "r"(a[1]), "r"(a[2]), "r"(a[3]), "r"(b0), "r"(b1));
}

// split fp32 -> (hi, lo) bf16 pair; hi+lo reproduces x to ~2^-17 relative.
__device__ __forceinline__ void split2(float x, float y,
                                       __nv_bfloat162* ph, __nv_bfloat162* pl) {
    __nv_bfloat16 hx = __float2bfloat16_rn(x);
    __nv_bfloat16 hy = __float2bfloat16_rn(y);
    __nv_bfloat16 lx = __float2bfloat16_rn(x - __bfloat162float(hx));
    __nv_bfloat16 ly = __float2bfloat16_rn(y - __bfloat162float(hy));
    *ph = __nv_bfloat162(hx, hy);
    *pl = __nv_bfloat162(lx, ly);
}

// ---------------------------------------------------------------- tensor-core GEMM core
// Block tile BM x BN, BK = 32, 256 threads, 8 warps, 2-stage smem pipeline.
// Warp grid: WM = BM/32 m-warps x WN = 8/WM n-warps; warp tile 32 x (BN/WN).
// fp32 in/out; bf16 hi/lo 3-pass (hh + hl + lh).
// TRANSB: B is [N,K] row-major (C = A*B^T); else B is [K,N] row-major.
// Uses dynamic shared memory; size must match SMEM_* host constants.
template <int BM, int BN, bool TRANSB, int ACT>
__device__ __forceinline__ void gemm_core(
    const float* __restrict__ A, int lda,
    const float* __restrict__ B, int ldb,
    float* __restrict__ C, int ldc,
    const float* __restrict__ bias,
    int K, int bm, int bn)
{
    constexpr int PA   = 40;        // A smem pitch (bf16): conflict-free ldmatrix
    constexpr int PBT  = 40;        // B pitch, TRANSB [n][k]
    constexpr int PBN  = BN + 8;    // B pitch, !TRANSB [k][n]
    constexpr int WM   = BM / 32;
    constexpr int WN   = 8 / WM;
    constexpr int WTN  = BN / WN;
    constexpr int NT   = WTN / 8;
    constexpr int NG   = WTN / 16;
    constexpr int AV   = BM / 32;   // float4 per thread, A staging
    constexpr int BV   = BN / 32;   // float4 per thread, B staging
    constexpr int ASZ  = BM * PA;                       // bf16 per A array
    constexpr int BSZE = TRANSB ? BN * PBT : 32 * PBN;  // bf16 per B array
    constexpr int STG  = 2 * ASZ + 2 * BSZE;            // bf16 per stage

    extern __shared__ __align__(16) __nv_bfloat16 smem_[];

    const int tid  = threadIdx.x;
    const int lane = tid & 31;
    const int warp = tid >> 5;
    const int wr   = warp / WN;
    const int wc   = warp % WN;
    const int wm0  = wr * 32;
    const int wn0  = wc * WTN;

    float acc[2][NT][4];
#pragma unroll
    for (int i = 0; i < 2; i++)
#pragma unroll
        for (int j = 0; j < NT; j++)
#pragma unroll
            for (int t = 0; t < 4; t++) acc[i][j][t] = 0.0f;

    // ldmatrix per-lane source coordinates
    const int arow = (lane & 7) + ((lane >> 3) & 1) * 8;
    const int acol = (lane >> 4) * 8;
    const int brow = (lane & 7) + (lane >> 4) * 8;
    const int bcol = ((lane >> 3) & 1) * 8;
    const int btr  = ((lane >> 3) & 1) * 8 + (lane & 7);
    const int btc  = (lane >> 4) * 8;

    float4 ra[AV], rb[BV];

    auto loadA = [&](int kt) {
#pragma unroll
        for (int u = 0; u < AV; u++) {
            int i = tid + u * 256;
            int r = i >> 3, c = (i & 7) << 2;
            ra[u] = *(const float4*)(A + (size_t)(bm + r) * lda + kt + c);
        }
    };
    auto loadB = [&](int kt) {
        if (TRANSB) {
#pragma unroll
            for (int u = 0; u < BV; u++) {
                int i = tid + u * 256;
                int r = i >> 3, c = (i & 7) << 2;
                rb[u] = *(const float4*)(B + (size_t)(bn + r) * ldb + kt + c);
            }
        } else {
#pragma unroll
            for (int u = 0; u < BV; u++) {
                int i = tid + u * 256;
                int r = i >> 4, c = (i & 15) << 2;
                rb[u] = *(const float4*)(B + (size_t)(kt + r) * ldb + bn + c);
            }
        }
    };
    auto storeStage = [&](int s) {
        __nv_bfloat16* Ah = smem_ + (size_t)s * STG;
        __nv_bfloat16* Al = Ah + ASZ;
        __nv_bfloat16* Bh = Al + ASZ;
        __nv_bfloat16* Bl = Bh + BSZE;
#pragma unroll
        for (int u = 0; u < AV; u++) {
            int i = tid + u * 256;
            int r = i >> 3, c = (i & 7) << 2;
            split2(ra[u].x, ra[u].y, (__nv_bfloat162*)&Ah[r * PA + c],
                                     (__nv_bfloat162*)&Al[r * PA + c]);
            split2(ra[u].z, ra[u].w, (__nv_bfloat162*)&Ah[r * PA + c + 2],
                                     (__nv_bfloat162*)&Al[r * PA + c + 2]);
        }
        if (TRANSB) {
#pragma unroll
            for (int u = 0; u < BV; u++) {
                int i = tid + u * 256;
                int r = i >> 3, c = (i & 7) << 2;
                split2(rb[u].x, rb[u].y, (__nv_bfloat162*)&Bh[r * PBT + c],
                                         (__nv_bfloat162*)&Bl[r * PBT + c]);
                split2(rb[u].z, rb[u].w, (__nv_bfloat162*)&Bh[r * PBT + c + 2],
                                         (__nv_bfloat162*)&Bl[r * PBT + c + 2]);
            }
        } else {
#pragma unroll
            for (int u = 0; u < BV; u++) {
                int i = tid + u * 256;
                int r = i >> 4, c = (i & 15) << 2;
                split2(rb[u].x, rb[u].y, (__nv_bfloat162*)&Bh[r * PBN + c],
                                         (__nv_bfloat162*)&Bl[r * PBN + c]);
                split2(rb[u].z, rb[u].w, (__nv_bfloat162*)&Bh[r * PBN + c + 2],
                                         (__nv_bfloat162*)&Bl[r * PBN + c + 2]);
            }
        }
    };

    loadA(0); loadB(0);
    storeStage(0);
    __syncthreads();

    for (int kt = 0; kt < K; kt += 32) {
        const int p = (kt >> 5) & 1;
        const bool next = (kt + 32) < K;
        if (next) { loadA(kt + 32); loadB(kt + 32); }   // global prefetch

        const __nv_bfloat16* Ah = smem_ + (size_t)p * STG;
        const __nv_bfloat16* Al = Ah + ASZ;
        const __nv_bfloat16* Bh = Al + ASZ;
        const __nv_bfloat16* Bl = Bh + BSZE;

#pragma unroll
        for (int ks = 0; ks < 32; ks += 16) {
            uint32_t ah[2][4], al[2][4], bh[NG][4], bl[NG][4];
#pragma unroll
            for (int t = 0; t < 2; t++) {
                ldsm4(ah[t], &Ah[(wm0 + t * 16 + arow) * PA + ks + acol]);
                ldsm4(al[t], &Al[(wm0 + t * 16 + arow) * PA + ks + acol]);
            }
#pragma unroll
            for (int g = 0; g < NG; g++) {
                if (TRANSB) {
                    ldsm4 (bh[g], &Bh[(wn0 + g * 16 + brow) * PBT + ks + bcol]);
                    ldsm4 (bl[g], &Bl[(wn0 + g * 16 + brow) * PBT + ks + bcol]);
                } else {
                    ldsm4t(bh[g], &Bh[(ks + btr) * PBN + wn0 + g * 16 + btc]);
                    ldsm4t(bl[g], &Bl[(ks + btr) * PBN + wn0 + g * 16 + btc]);
                }
            }
#pragma unroll
            for (int i = 0; i < 2; i++)
#pragma unroll
                for (int j = 0; j < NT; j++) {
                    int g = j >> 1, s = (j & 1) * 2;
                    mma16816(acc[i][j], ah[i], bh[g][s], bh[g][s + 1]);  // hh
                    mma16816(acc[i][j], ah[i], bl[g][s], bl[g][s + 1]);  // hl
                    mma16816(acc[i][j], al[i], bh[g][s], bh[g][s + 1]);  // lh
                }
        }
        if (next) storeStage(p ^ 1);
        __syncthreads();
    }

    // ---- epilogue
#pragma unroll
    for (int i = 0; i < 2; i++) {
        int r0 = bm + wm0 + i * 16 + (lane >> 2);
#pragma unroll
        for (int j = 0; j < NT; j++) {
            int c0 = bn + wn0 + j * 8 + 2 * (lane & 3);
            float bx = 0.f, by = 0.f;
            if (bias) { bx = bias[c0]; by = bias[c0 + 1]; }
            float2 o0, o1;
            o0.x = acc[i][j][0] + bx; o0.y = acc[i][j][1] + by;
            o1.x = acc[i][j][2] + bx; o1.y = acc[i][j][3] + by;
            if (ACT == 1) {
                o0.x = gelu_f(o0.x); o0.y = gelu_f(o0.y);
                o1.x = gelu_f(o1.x); o1.y = gelu_f(o1.y);
            }
            *(float2*)(C + (size_t)r0 * ldc + c0)       = o0;
            *(float2*)(C + (size_t)(r0 + 8) * ldc + c0) = o1;
        }
    }
}

// ---------------------------------------------------------------- kernels on top of the core
struct PJob { const float* A; const float* B; const float* bias; float* C; int M; };

// five projection jobs in one launch (QKV + pos-k + pos-q), BM=128
__global__ __launch_bounds__(256, 2) void proj5_k(
    int N, int K, int lda, PJob j0, PJob j1, PJob j2, PJob j3, PJob j4)
{
    int z = blockIdx.z;
    PJob jb = (z == 0) ? j0 : (z == 1) ? j1 : (z == 2) ? j2 : (z == 3) ? j3 : j4;
    int bm = blockIdx.y * 128;
    if (bm >= jb.M) return;
    gemm_core<128, 64, false, 0>(jb.A, lda, jb.B, N, jb.C, N, jb.bias, K,
                                 bm, blockIdx.x * 64);
}

// single GEMM, C = A @ B + bias, B [K,N] row-major; BM selectable
template <int BM, int ACT, int NBL>
__global__ __launch_bounds__(256, NBL) void gemm_nt_k(
    int N, int K, const float* __restrict__ A, int lda,
    const float* __restrict__ B, const float* __restrict__ bias, float* __restrict__ C)
{
    gemm_core<BM, 64, false, ACT>(A, lda, B, N, C, N, bias, K,
                                  blockIdx.y * BM, blockIdx.x * 64);
}

// fused attention GEMMs: scores / c2p / p2c, [512,512] = [512,64] @ [512,64]^T
// z = g*32 + (b*16 + h), g in {0: scores, 1: c2p, 2: p2c}
__global__ __launch_bounds__(256, 2) void attn_gemm_k(
    const float* __restrict__ q, const float* __restrict__ k,
    const float* __restrict__ posk, const float* __restrict__ posq,
    float* __restrict__ sc, float* __restrict__ c2p, float* __restrict__ p2c)
{
    int z = blockIdx.z;
    int g = z >> 5;
    int i = z & 31;
    int b = i >> 4;
    int h = i & 15;
    long long aOff = (long long)b * SH + h * DH;
    const float* A;
    const float* B;
    float* C;
    if (g == 0)      { A = q + aOff; B = k + aOff;      C = sc  + (long long)i * SS; }
    else if (g == 1) { A = q + aOff; B = posk + h * DH; C = c2p + (long long)i * SR; }
    else             { A = k + aOff; B = posq + h * DH; C = p2c + (long long)i * SR; }
    gemm_core<128, 64, true, 0>(A, HID, B, HID, C, 512, nullptr, DH,
                                blockIdx.y * 128, blockIdx.x * 64);
}

// ctx[b,:,h,:] = probs[b,h] @ v[b,:,h,:]   (z = b*16+h), BM=64
__global__ __launch_bounds__(256, 3) void ctx_gemm_k(
    const float* __restrict__ sc, const float* __restrict__ v, float* __restrict__ ctx)
{
    int z = blockIdx.z;
    int b = z >> 4;
    int h = z & 15;
    const float* A = sc + (long long)z * SS;
    const float* B = v + (long long)b * SH + h * DH;
    float* C = ctx + (long long)b * SH + h * DH;
    gemm_core<64, 64, false, 0>(A, SEQ, B, HID, C, HID, nullptr, SEQ,
                                blockIdx.y * 64, blockIdx.x * 64);
}

// ---------------------------------------------------------------- embedding
__global__ void embed_kernel(const float* __restrict__ we,
                             const float* __restrict__ gamma, const float* __restrict__ beta,
                             const int* __restrict__ ids, const int* __restrict__ am,
                             float* __restrict__ x, float* __restrict__ mk)
{
    int t = blockIdx.x, tid = threadIdx.x;
    const float4* row = (const float4*)(we + (long long)ids[t] * HID);
    float4 v = row[tid];
    float s  = v.x + v.y + v.z + v.w;
    float sq = v.x * v.x + v.y * v.y + v.z * v.z + v.w * v.w;
    s  = blk_sum<256>(s);
    sq = blk_sum<256>(sq);
    float mu  = s * (1.0f / HID);
    float inv = rsqrtf(sq * (1.0f / HID) - mu * mu + LN_EPS);
    float m = (float)am[t];
    if (tid == 0) mk[t] = m;
    float4 g = ((const float4*)gamma)[tid];
    float4 b = ((const float4*)beta)[tid];
    float4 o;
    o.x = ((v.x - mu) * inv * g.x + b.x) * m;
    o.y = ((v.y - mu) * inv * g.y + b.y) * m;
    o.z = ((v.z - mu) * inv * g.z + b.z) * m;
    o.w = ((v.w - mu) * inv * g.w + b.w) * m;
    ((float4*)(x + (long long)t * HID))[tid] = o;
}

// ---------------------------------------------------------------- LN (optional residual)
__global__ void ln_kernel(const float* __restrict__ in, const float* __restrict__ resid,
                          const float* __restrict__ gamma, const float* __restrict__ beta,
                          float* __restrict__ out)
{
    int row = blockIdx.x, tid = threadIdx.x;
    float4 v = ((const float4*)(in + (long long)row * HID))[tid];
    if (resid) {
        float4 r = ((const float4*)(resid + (long long)row * HID))[tid];
        v.x += r.x; v.y += r.y; v.z += r.z; v.w += r.w;
    }
    float s  = v.x + v.y + v.z + v.w;
    float sq = v.x * v.x + v.y * v.y + v.z * v.z + v.w * v.w;
    s  = blk_sum<256>(s);
    sq = blk_sum<256>(sq);
    float mu  = s * (1.0f / HID);
    float inv = rsqrtf(sq * (1.0f / HID) - mu * mu + LN_EPS);
    float4 g = ((const float4*)gamma)[tid];
    float4 b = ((const float4*)beta)[tid];
    float4 o;
    o.x = (v.x - mu) * inv * g.x + b.x;
    o.y = (v.y - mu) * inv * g.y + b.y;
    o.z = (v.z - mu) * inv * g.z + b.z;
    o.w = (v.w - mu) * inv * g.w + b.w;
    ((float4*)(out + (long long)row * HID))[tid] = o;
}

// ---------------------------------------------------------------- DeBERTa log-bucket index
__global__ void rel_idx_kernel(int* __restrict__ idx)
{
    int k = blockIdx.x * blockDim.x + threadIdx.x;
    int q = blockIdx.y;
    int rel = q - k;
    const int mid = 128;
    int ap = (rel > -mid && rel < mid) ? (mid - 1) : (rel < 0 ? -rel : rel);
    int bucket;
    if (ap <= mid) {
        bucket = rel;
    } else {
        float lp = ceilf(logf((float)ap / 128.0f) / logf(511.0f / 128.0f) * 127.0f) + 128.0f;
        float sg = (rel > 0) ? 1.0f : -1.0f;
        bucket = (int)(lp * sg);
    }
    int c = bucket + 256;
    c = min(max(c, 0), 511);
    idx[q * SEQ + k] = c;
}

// ---------------------------------------------------------------- fused gather + mask + softmax
__global__ void attn_softmax_kernel(float* __restrict__ sc,
                                    const float* __restrict__ c2p, const float* __restrict__ p2c,
                                    const int* __restrict__ idx, const float* __restrict__ mk)
{
    const float invScale = 0.072168783648703221f;  // 1/sqrt(3*64)
    int q = blockIdx.x, h = blockIdx.y, b = blockIdx.z;
    int tid = threadIdx.x;                          // 128
    long long bh = (long long)b * NHH + h;
    float* srow       = sc  + (bh * SEQ + q) * SEQ;
    const float* crow = c2p + (bh * SEQ + q) * RR;
    const float* psl  = p2c + bh * SEQ * RR;
    const int* irow   = idx + q * SEQ;
    float mq = mk[b * SEQ + q];

    float v[4], mm[4];
    float mx = -3.0e38f;
#pragma unroll
    for (int j = 0; j < 4; j++) {
        int k = j * 128 + tid;
        float m = mq * mk[b * SEQ + k];
        mm[j] = m;
        float s = -3.0e38f;
        if (m != 0.0f) {
            int r = irow[k];
            s = (srow[k] + crow[r] + psl[(long long)k * RR + r]) * invScale;
        }
        v[j] = s;
        mx = fmaxf(mx, s);
    }
    mx = blk_max<128>(mx);
    float sum = 0.0f;
#pragma unroll
    for (int j = 0; j < 4; j++) {
        float e = (mm[j] != 0.0f) ? expf(v[j] - mx) : 0.0f;
        v[j] = e;
        sum += e;
    }
    sum = blk_sum<128>(sum);
    float inv = (sum > 0.0f) ? (1.0f / sum) : 0.0f;
#pragma unroll
    for (int j = 0; j < 4; j++) srow[j * 128 + tid] = v[j] * inv;
}

// ---------------------------------------------------------------- decoder (N=14)
__global__ void decoder_kernel(const float* __restrict__ t, const float* __restrict__ Wd,
                               const float* __restrict__ bd, float* __restrict__ logits,
                               float* __restrict__ dout)
{
    int tok = blockIdx.x, tid = threadIdx.x;        // 128 threads
    float acc[NCLS];
#pragma unroll
    for (int c = 0; c < NCLS; c++) acc[c] = 0.0f;
    const float* trow = t + (long long)tok * HID;
    for (int k = tid; k < HID; k += 128) {
        float tv = trow[k];
        const float* w = Wd + (long long)k * NCLS;
#pragma unroll
        for (int c = 0; c < NCLS; c++) acc[c] = fmaf(tv, w[c], acc[c]);
    }
    __shared__ float red[NCLS][128];
#pragma unroll
    for (int c = 0; c < NCLS; c++) red[c][tid] = acc[c];
    __syncthreads();
    if (tid < NCLS) {
        float s = 0.0f;
        for (int i = 0; i < 128; i++) s += red[tid][i];
        s += bd[tid];
        logits[tok * NCLS + tid] = s;
        if (dout) dout[tok * NCLS + tid] = s;
    }
}

// ---------------------------------------------------------------- masked CE loss
__global__ void loss_kernel(const float* __restrict__ logits, const int* __restrict__ labels,
                            const float* __restrict__ mk, float* __restrict__ outLoss)
{
    int t = threadIdx.x;                             // 1024 threads = TOK
    float m = mk[t];
    const float* lr = logits + t * NCLS;
    float mx = -3.0e38f;
#pragma unroll
    for (int c = 0; c < NCLS; c++) mx = fmaxf(mx, lr[c]);
    float s = 0.0f;
#pragma unroll
    for (int c = 0; c < NCLS; c++) s += expf(lr[c] - mx);
    float lse = mx + logf(s);
    float nll = (lse - lr[labels[t]]) * m;
    float ns = blk_sum<1024>(nll);
    float ms = blk_sum<1024>(m);
    if (t == 0 && outLoss) *outLoss = ns / fmaxf(ms, 1.0f);
}

// ---------------------------------------------------------------- host orchestration
extern "C" void kernel_launch(void* const* d_in, const int* in_sizes, int n_in,
                              void* d_out, int out_size)
{
    (void)in_sizes; (void)n_in;
    const float* word_emb = (const float*)d_in[0];
    const float* emb_ln_s = (const float*)d_in[1];
    const float* emb_ln_b = (const float*)d_in[2];
    const float* rel_emb  = (const float*)d_in[3];
    const float* rel_ln_s = (const float*)d_in[4];
    const float* rel_ln_b = (const float*)d_in[5];
    const float* Wq = (const float*)d_in[6];
    const float* bq = (const float*)d_in[7];
    const float* Wk = (const float*)d_in[8];
    const float* bk = (const float*)d_in[9];
    const float* Wv = (const float*)d_in[10];
    const float* bv = (const float*)d_in[11];
    const float* Wo = (const float*)d_in[12];
    const float* bo = (const float*)d_in[13];
    const float* ln1_s = (const float*)d_in[14];
    const float* ln1_b = (const float*)d_in[15];
    const float* W1 = (const float*)d_in[16];
    const float* b1 = (const float*)d_in[17];
    const float* W2 = (const float*)d_in[18];
    const float* b2 = (const float*)d_in[19];
    const float* ln2_s = (const float*)d_in[20];
    const float* ln2_b = (const float*)d_in[21];
    const float* Wt = (const float*)d_in[22];
    const float* bt = (const float*)d_in[23];
    const float* tln_s = (const float*)d_in[24];
    const float* tln_b = (const float*)d_in[25];
    const float* Wd = (const float*)d_in[26];
    const float* bd = (const float*)d_in[27];
    const int* input_ids = (const int*)d_in[28];
    const int* amask     = (const int*)d_in[29];
    const int* labels    = (const int*)d_in[30];

    float *x, *q, *k, *v, *ctx, *tmp, *sc, *c2p, *p2c, *posk, *posq, *rel, *tb, *lg, *mk;
    int* idx;
    { void* p;
      cudaGetSymbolAddress(&p, g_x);    x    = (float*)p;
      cudaGetSymbolAddress(&p, g_q);    q    = (float*)p;
      cudaGetSymbolAddress(&p, g_k);    k    = (float*)p;
      cudaGetSymbolAddress(&p, g_v);    v    = (float*)p;
      cudaGetSymbolAddress(&p, g_ctx);  ctx  = (float*)p;
      cudaGetSymbolAddress(&p, g_tmp);  tmp  = (float*)p;
      cudaGetSymbolAddress(&p, g_sc);   sc   = (float*)p;
      cudaGetSymbolAddress(&p, g_c2p);  c2p  = (float*)p;
      cudaGetSymbolAddress(&p, g_p2c);  p2c  = (float*)p;
      cudaGetSymbolAddress(&p, g_posk); posk = (float*)p;
      cudaGetSymbolAddress(&p, g_posq); posq = (float*)p;
      cudaGetSymbolAddress(&p, g_rel);  rel  = (float*)p;
      cudaGetSymbolAddress(&p, g_t);    tb   = (float*)p;
      cudaGetSymbolAddress(&p, g_lg);   lg   = (float*)p;
      cudaGetSymbolAddress(&p, g_mk);   mk   = (float*)p;
      cudaGetSymbolAddress(&p, g_idx);  idx  = (int*)p;
    }

    // opt-in dynamic smem > 48KB for the 128-row-tile kernels (host-side, capture-safe)
    cudaFuncSetAttribute(proj5_k, cudaFuncAttributeMaxDynamicSharedMemorySize, SMEM_P128);
    cudaFuncSetAttribute(attn_gemm_k, cudaFuncAttributeMaxDynamicSharedMemorySize, SMEM_T128);
    cudaFuncSetAttribute(gemm_nt_k<128, 1, 2>, cudaFuncAttributeMaxDynamicSharedMemorySize, SMEM_P128);

    float* out_logits = nullptr;
    float* out_loss   = nullptr;
    if (out_size >= TOK * NCLS) {
        out_logits = (float*)d_out;
        if (out_size > TOK * NCLS) out_loss = (float*)d_out + TOK * NCLS;
    } else if (out_size >= 1) {
        out_loss = (float*)d_out;
    }

    // --- preamble
    embed_kernel<<<TOK, 256>>>(word_emb, emb_ln_s, emb_ln_b, input_ids, amask, x, mk);
    ln_kernel<<<RR, 256>>>(rel_emb, nullptr, rel_ln_s, rel_ln_b, rel);
    rel_idx_kernel<<<dim3(SEQ / 256, SEQ), 256>>>(idx);

    for (int l = 0; l < NL; l++) {
        const float* Wq_l = Wq + (long long)l * HID * HID;
        const float* Wk_l = Wk + (long long)l * HID * HID;
        const float* Wv_l = Wv + (long long)l * HID * HID;
        const float* Wo_l = Wo + (long long)l * HID * HID;
        const float* bq_l = bq + l * HID;
        const float* bk_l = bk + l * HID;
        const float* bv_l = bv + l * HID;
        const float* bo_l = bo + l * HID;
        const float* W1_l = W1 + (long long)l * HID * FFD;
        const float* b1_l = b1 + l * FFD;
        const float* W2_l = W2 + (long long)l * FFD * HID;
        const float* b2_l = b2 + l * HID;

        // QKV + positional projections in one launch (z = 5)
        {
            PJob jq {x,   Wq_l, bq_l, q,    TOK};
            PJob jk {x,   Wk_l, bk_l, k,    TOK};
            PJob jv {x,   Wv_l, bv_l, v,    TOK};
            PJob jpk{rel, Wk_l, bk_l, posk, RR};
            PJob jpq{rel, Wq_l, bq_l, posq, RR};
            proj5_k<<<dim3(HID / 64, TOK / 128, 5), 256, SMEM_P128>>>(
                HID, HID, HID, jq, jk, jv, jpk, jpq);
        }

        // scores + c2p + p2c fused (z = 96)
        attn_gemm_k<<<dim3(SEQ / 64, SEQ / 128, 96), 256, SMEM_T128>>>(
            q, k, posk, posq, sc, c2p, p2c);

        // gather + mask + softmax
        attn_softmax_kernel<<<dim3(SEQ, NHH, BSZ), 128>>>(sc, c2p, p2c, idx, mk);

        // ctx = probs @ v (z = 32, BM=64)
        ctx_gemm_k<<<dim3(1, SEQ / 64, 32), 256, SMEM_P64>>>(sc, v, ctx);

        // output projection + residual LN (BM=64: 256 blocks)
        gemm_nt_k<64, 0, 3><<<dim3(HID / 64, TOK / 64), 256, SMEM_P64>>>(
            HID, HID, ctx, HID, Wo_l, bo_l, tmp);
        ln_kernel<<<TOK, 256>>>(x, tmp, ln1_s + l * HID, ln1_b + l * HID, x);

        // FFN
        gemm_nt_k<128, 1, 2><<<dim3(FFD / 64, TOK / 128), 256, SMEM_P128>>>(
            FFD, HID, x, HID, W1_l, b1_l, tmp);
        gemm_nt_k<64, 0, 3><<<dim3(HID / 64, TOK / 64), 256, SMEM_P64>>>(
            HID, FFD, tmp, FFD, W2_l, b2_l, ctx);
        ln_kernel<<<TOK, 256>>>(x, ctx, ln2_s + l * HID, ln2_b + l * HID, x);
    }

    // head: t = LN(gelu(x @ Wt + bt)); logits = t @ Wd + bd; loss
    gemm_nt_k<64, 1, 3><<<dim3(HID / 64, TOK / 64), 256, SMEM_P64>>>(
        HID, HID, x, HID, Wt, bt, tmp);
    ln_kernel<<<TOK, 256>>>(tmp, nullptr, tln_s, tln_b, tb);
    decoder_kernel<<<TOK, 128>>>(tb, Wd, bd, lg, out_logits);
    loss_kernel<<<1, 1024>>>(lg, labels, mk, out_loss);
}